// round 2
// baseline (speedup 1.0000x reference)
#include <cuda_runtime.h>

// Problem dims
#define B_N    4096
#define U_DIM  256
#define D_DIM  64
#define KIN    320      // U_DIM + D_DIM
#define H_DIM  8192
#define ORD    4096     // H_DIM / 2
#define Y_DIM  256
#define DELTA_F 0.1f

#define SPLITS 32
#define KCHUNK 256      // H_DIM / SPLITS
#define KT 16

// ---------------- scratch (static device globals; no allocation) ----------------
__device__ float g_Cp[Y_DIM * H_DIM];          // C' = C_w @ blockdiag(M)   8 MB
__device__ float g_rec[H_DIM];                 // rotated h
__device__ float g_p[ORD];                     // sin(wD)/w
__device__ float g_q[ORD];                     // (cos(wD)-1)/w
__device__ float g_y0p[Y_DIM * 4];             // y0 partials (4 per row)
__device__ float g_y0[Y_DIM];
__device__ float g_Gpart[SPLITS][Y_DIM * KIN]; // split-K partials 10.5 MB
__device__ float g_G[Y_DIM * KIN];             // G [256][320]

// packed-f32x2 FMA helper
__device__ __forceinline__ void ffma2(unsigned long long& acc,
                                      unsigned long long a,
                                      unsigned long long b) {
    asm("fma.rn.f32x2 %0, %1, %2, %0;" : "+l"(acc) : "l"(a), "l"(b));
}
__device__ __forceinline__ float f2lo(unsigned long long v) {
    return __uint_as_float((unsigned)(v & 0xFFFFFFFFull));
}
__device__ __forceinline__ float f2hi(unsigned long long v) {
    return __uint_as_float((unsigned)(v >> 32));
}

// ---------------- kernel 0: per-pair rotation coefficients + rotated h ----------------
__global__ void coef_kernel(const float* __restrict__ om, const float* __restrict__ h) {
    int j = blockIdx.x * blockDim.x + threadIdx.x;
    if (j >= ORD) return;
    float w = om[j];
    float s, c;
    sincosf(w * DELTA_F, &s, &c);
    float inv = 1.0f / w;
    g_p[j] = s * inv;
    g_q[j] = (c - 1.0f) * inv;
    float h0 = h[2 * j], h1 = h[2 * j + 1];
    g_rec[2 * j]     =  c * h0 + s * h1;
    g_rec[2 * j + 1] = -s * h0 + c * h1;
}

// ---------------- kernel 1: C' fold + y0 partials ----------------
// grid (4, 256): blockIdx.y = output row m, blockIdx.x = quarter of the H dim.
__global__ __launch_bounds__(256) void prep_kernel(const float* __restrict__ Cw) {
    int m = blockIdx.y;
    int jbase = blockIdx.x * 1024 + threadIdx.x * 4;   // 4 pairs per thread
    const float* crow = Cw + (size_t)m * H_DIM;
    float* orow = g_Cp + (size_t)m * H_DIM;
    float y0acc = 0.0f;
#pragma unroll
    for (int v = 0; v < 2; v++) {
        int j = jbase + 2 * v;
        float4 cv = *(const float4*)(crow + 2 * j);
        float4 rv = *(const float4*)(g_rec + 2 * j);
        float2 pv = *(const float2*)(g_p + j);
        float2 qv = *(const float2*)(g_q + j);
        y0acc += cv.x * rv.x + cv.y * rv.y + cv.z * rv.z + cv.w * rv.w;
        float4 ov;
        ov.x =  cv.x * pv.x + cv.y * qv.x;
        ov.y = -cv.x * qv.x + cv.y * pv.x;
        ov.z =  cv.z * pv.y + cv.w * qv.y;
        ov.w = -cv.z * qv.y + cv.w * pv.y;
        *(float4*)(orow + 2 * j) = ov;
    }
    __shared__ float red[256];
    red[threadIdx.x] = y0acc;
    __syncthreads();
    for (int off = 128; off > 0; off >>= 1) {
        if (threadIdx.x < off) red[threadIdx.x] += red[threadIdx.x + off];
        __syncthreads();
    }
    if (threadIdx.x == 0) g_y0p[m * 4 + blockIdx.x] = red[0];
}

// ---------------- kernel 2: G partials = C'(256x8192) @ B_w(8192x320), split-K ----------------
// block: 256 threads, tile 64(m) x 320(n full), 8x10 per thread. grid (4, SPLITS).
__global__ __launch_bounds__(256, 1) void gemmG_kernel(const float* __restrict__ Bw) {
    __shared__ float2 As2[KT][66];   // pre-duplicated A operand [kk][m]
    __shared__ float  Bs[KT][KIN];   // [kk][n]
    int t = threadIdx.x;
    int m0 = blockIdx.x * 64;
    int kbase = blockIdx.y * KCHUNK;
    int tn = t & 31, tmg = t >> 5;
    int arow = t >> 2, acq = t & 3;

    unsigned long long acc[8][5];
#pragma unroll
    for (int i = 0; i < 8; i++)
#pragma unroll
        for (int p = 0; p < 5; p++) acc[i][p] = 0ull;

    for (int kt = 0; kt < KCHUNK; kt += KT) {
        int k0 = kbase + kt;
        __syncthreads();
        // A tile: 64 rows x 16 k, one float4 per thread, stored duplicated
        float4 av = *(const float4*)&g_Cp[(size_t)(m0 + arow) * H_DIM + k0 + acq * 4];
        As2[acq * 4 + 0][arow] = make_float2(av.x, av.x);
        As2[acq * 4 + 1][arow] = make_float2(av.y, av.y);
        As2[acq * 4 + 2][arow] = make_float2(av.z, av.z);
        As2[acq * 4 + 3][arow] = make_float2(av.w, av.w);
        // B tile: 16 k x 320 n, five float4 per thread
#pragma unroll
        for (int i = 0; i < 5; i++) {
            int idx = t + i * 256;
            int br = idx / 80, bc = idx % 80;
            *(float4*)&Bs[br][bc * 4] =
                *(const float4*)&Bw[(size_t)(k0 + br) * KIN + bc * 4];
        }
        __syncthreads();
#pragma unroll
        for (int kk = 0; kk < KT; kk++) {
            unsigned long long b[5];
#pragma unroll
            for (int p = 0; p < 5; p++)
                b[p] = *(const unsigned long long*)&Bs[kk][tn * 10 + p * 2];
#pragma unroll
            for (int i = 0; i < 8; i++) {
                unsigned long long a =
                    *(const unsigned long long*)&As2[kk][tmg * 8 + i];
#pragma unroll
                for (int p = 0; p < 5; p++) ffma2(acc[i][p], a, b[p]);
            }
        }
    }
    float* out = g_Gpart[blockIdx.y];
#pragma unroll
    for (int i = 0; i < 8; i++) {
        int m = m0 + tmg * 8 + i;
#pragma unroll
        for (int p = 0; p < 5; p++)
            *(unsigned long long*)&out[m * KIN + tn * 10 + p * 2] = acc[i][p];
    }
}

// ---------------- kernel 3: deterministic split-K + y0 reduction ----------------
__global__ void reduceG_kernel() {
    int idx = blockIdx.x * blockDim.x + threadIdx.x;
    if (idx < Y_DIM * KIN) {
        float s = 0.0f;
#pragma unroll
        for (int p = 0; p < SPLITS; p++) s += g_Gpart[p][idx];
        g_G[idx] = s;
    }
    if (idx < Y_DIM) {
        g_y0[idx] = (g_y0p[idx * 4 + 0] + g_y0p[idx * 4 + 1]) +
                    (g_y0p[idx * 4 + 2] + g_y0p[idx * 4 + 3]);
    }
}

// ---------------- kernel 4: y = y0 + udu @ G^T ----------------
// block: 256 threads, tile 128(batch) x 64(y), 8x4 per thread. grid (4, 32).
__global__ __launch_bounds__(256, 1) void finalY_kernel(const float* __restrict__ u,
                                                        const float* __restrict__ du,
                                                        float* __restrict__ y) {
    __shared__ float2 As2[KT][130];  // duplicated udu [kk][b]
    __shared__ float  Bs[KT][68];    // G^T tile [kk][n]
    __shared__ float  y0s[64];
    int t = threadIdx.x;
    int n0 = blockIdx.x * 64;
    int b0 = blockIdx.y * 128;
    if (t < 64) y0s[t] = g_y0[n0 + t];
    int tni = t & 15, tmi = t >> 4;

    unsigned long long acc[8][2];
#pragma unroll
    for (int i = 0; i < 8; i++) { acc[i][0] = 0ull; acc[i][1] = 0ull; }

    for (int k0 = 0; k0 < KIN; k0 += KT) {
        __syncthreads();
        // A tile: 128 batch rows x 16 k, two float4 per thread (concat boundary 64 is KT-aligned)
#pragma unroll
        for (int i = 0; i < 2; i++) {
            int idx = t + i * 256;
            int row = idx >> 2, cq = idx & 3;
            float4 av;
            if (k0 < D_DIM)
                av = *(const float4*)&du[(size_t)(b0 + row) * D_DIM + k0 + cq * 4];
            else
                av = *(const float4*)&u[(size_t)(b0 + row) * U_DIM + (k0 - D_DIM) + cq * 4];
            As2[cq * 4 + 0][row] = make_float2(av.x, av.x);
            As2[cq * 4 + 1][row] = make_float2(av.y, av.y);
            As2[cq * 4 + 2][row] = make_float2(av.z, av.z);
            As2[cq * 4 + 3][row] = make_float2(av.w, av.w);
        }
        // B tile (transposed G): Bs[kk][n] = G[n0+n][k0+kk]
        {
            int row = t >> 2, cq = t & 3;
            float4 gv = *(const float4*)&g_G[(n0 + row) * KIN + k0 + cq * 4];
            Bs[cq * 4 + 0][row] = gv.x;
            Bs[cq * 4 + 1][row] = gv.y;
            Bs[cq * 4 + 2][row] = gv.z;
            Bs[cq * 4 + 3][row] = gv.w;
        }
        __syncthreads();
#pragma unroll
        for (int kk = 0; kk < KT; kk++) {
            unsigned long long bp0 = *(const unsigned long long*)&Bs[kk][tni * 4];
            unsigned long long bp1 = *(const unsigned long long*)&Bs[kk][tni * 4 + 2];
#pragma unroll
            for (int i = 0; i < 8; i++) {
                unsigned long long a =
                    *(const unsigned long long*)&As2[kk][tmi * 8 + i];
                ffma2(acc[i][0], a, bp0);
                ffma2(acc[i][1], a, bp1);
            }
        }
    }
#pragma unroll
    for (int i = 0; i < 8; i++) {
        int bb = b0 + tmi * 8 + i;
        float4 r;
        r.x = f2lo(acc[i][0]) + y0s[tni * 4 + 0];
        r.y = f2hi(acc[i][0]) + y0s[tni * 4 + 1];
        r.z = f2lo(acc[i][1]) + y0s[tni * 4 + 2];
        r.w = f2hi(acc[i][1]) + y0s[tni * 4 + 3];
        *(float4*)&y[(size_t)bb * Y_DIM + n0 + tni * 4] = r;
    }
}

// ---------------- launch ----------------
extern "C" void kernel_launch(void* const* d_in, const int* in_sizes, int n_in,
                              void* d_out, int out_size) {
    const float *u = nullptr, *du = nullptr, *h = nullptr, *om = nullptr,
                *Bw = nullptr, *Cw = nullptr;
    for (int i = 0; i < n_in; i++) {
        switch (in_sizes[i]) {
            case B_N * U_DIM:   u  = (const float*)d_in[i]; break;
            case B_N * D_DIM:   du = (const float*)d_in[i]; break;
            case H_DIM:         h  = (const float*)d_in[i]; break;
            case ORD:           om = (const float*)d_in[i]; break;
            case H_DIM * KIN:   Bw = (const float*)d_in[i]; break;
            case Y_DIM * H_DIM: Cw = (const float*)d_in[i]; break;
            default: break;
        }
    }
    if (!u || !du || !h || !om || !Bw || !Cw) {
        u  = (const float*)d_in[0];
        du = (const float*)d_in[1];
        h  = (const float*)d_in[2];
        om = (const float*)d_in[3];
        Bw = (const float*)d_in[4];
        Cw = (const float*)d_in[5];
    }
    float* y = (float*)d_out;

    coef_kernel<<<(ORD + 255) / 256, 256>>>(om, h);
    prep_kernel<<<dim3(4, Y_DIM), 256>>>(Cw);
    gemmG_kernel<<<dim3(4, SPLITS), 256>>>(Bw);
    reduceG_kernel<<<(Y_DIM * KIN + 255) / 256, 256>>>();
    finalY_kernel<<<dim3(Y_DIM / 64, B_N / 128), 256>>>(u, du, y);
}

// round 3
// speedup vs baseline: 1.4413x; 1.4413x over previous
#include <cuda_runtime.h>

// Problem dims
#define B_N    4096
#define U_DIM  256
#define D_DIM  64
#define KIN    320      // U_DIM + D_DIM
#define H_DIM  8192
#define ORD    4096     // H_DIM / 2
#define Y_DIM  256
#define DELTA_F 0.1f

#define SPLITS 32
#define KCHUNK 256      // H_DIM / SPLITS
#define KT 16

// ---------------- scratch (static device globals; no allocation) ----------------
__device__ float g_Cp[Y_DIM * H_DIM];          // C' = C_w @ blockdiag(M)   8 MB
__device__ float g_rec[H_DIM];                 // rotated h
__device__ float g_p[ORD];                     // sin(wD)/w
__device__ float g_q[ORD];                     // (cos(wD)-1)/w
__device__ float g_y0p[Y_DIM * 4];             // y0 partials (4 per row)
__device__ float g_y0[Y_DIM];
__device__ float g_Gpart[SPLITS][Y_DIM * KIN]; // split-K partials 10.5 MB
__device__ float g_G[Y_DIM * KIN];             // G [256][320]

// ---------------- f32x2 helpers ----------------
__device__ __forceinline__ void ffma2(unsigned long long& acc,
                                      unsigned long long a,
                                      unsigned long long b) {
    asm("fma.rn.f32x2 %0, %1, %2, %0;" : "+l"(acc) : "l"(a), "l"(b));
}
__device__ __forceinline__ unsigned long long pack2(float x, float y) {
    unsigned long long r;
    asm("mov.b64 %0, {%1, %2};" : "=l"(r) : "f"(x), "f"(y));
    return r;
}
__device__ __forceinline__ float f2lo(unsigned long long v) {
    return __uint_as_float((unsigned)(v & 0xFFFFFFFFull));
}
__device__ __forceinline__ float f2hi(unsigned long long v) {
    return __uint_as_float((unsigned)(v >> 32));
}

// ---------------- kernel 0: per-pair rotation coefficients + rotated h ----------------
__global__ void coef_kernel(const float* __restrict__ om, const float* __restrict__ h) {
    int j = blockIdx.x * blockDim.x + threadIdx.x;
    if (j >= ORD) return;
    float w = om[j];
    float s, c;
    sincosf(w * DELTA_F, &s, &c);
    float inv = 1.0f / w;
    g_p[j] = s * inv;
    g_q[j] = (c - 1.0f) * inv;
    float h0 = h[2 * j], h1 = h[2 * j + 1];
    g_rec[2 * j]     =  c * h0 + s * h1;
    g_rec[2 * j + 1] = -s * h0 + c * h1;
}

// ---------------- kernel 1: C' fold + y0 partials ----------------
// grid (4, 256): blockIdx.y = output row m, blockIdx.x = quarter of the H dim.
__global__ __launch_bounds__(256) void prep_kernel(const float* __restrict__ Cw) {
    int m = blockIdx.y;
    int jbase = blockIdx.x * 1024 + threadIdx.x * 4;   // 4 pairs per thread
    const float* crow = Cw + (size_t)m * H_DIM;
    float* orow = g_Cp + (size_t)m * H_DIM;
    float y0acc = 0.0f;
#pragma unroll
    for (int v = 0; v < 2; v++) {
        int j = jbase + 2 * v;
        float4 cv = *(const float4*)(crow + 2 * j);
        float4 rv = *(const float4*)(g_rec + 2 * j);
        float2 pv = *(const float2*)(g_p + j);
        float2 qv = *(const float2*)(g_q + j);
        y0acc += cv.x * rv.x + cv.y * rv.y + cv.z * rv.z + cv.w * rv.w;
        float4 ov;
        ov.x =  cv.x * pv.x + cv.y * qv.x;
        ov.y = -cv.x * qv.x + cv.y * pv.x;
        ov.z =  cv.z * pv.y + cv.w * qv.y;
        ov.w = -cv.z * qv.y + cv.w * pv.y;
        *(float4*)(orow + 2 * j) = ov;
    }
    __shared__ float red[256];
    red[threadIdx.x] = y0acc;
    __syncthreads();
    for (int off = 128; off > 0; off >>= 1) {
        if (threadIdx.x < off) red[threadIdx.x] += red[threadIdx.x + off];
        __syncthreads();
    }
    if (threadIdx.x == 0) g_y0p[m * 4 + blockIdx.x] = red[0];
}

// ---------------- kernel 2: G partials = C'(256x8192) @ B_w(8192x320), split-K ----------------
// 128 threads, tile 64(m) x 64(n), per-thread 8x4. grid (4, 5, SPLITS) = 640 CTAs.
__global__ __launch_bounds__(128) void gemmG_kernel(const float* __restrict__ Bw) {
    __shared__ __align__(16) float2 As2[KT][66];  // duplicated A [kk][m]  8448 B
    __shared__ __align__(16) float  Bs[KT][64];   // [kk][n]               4096 B
    int t = threadIdx.x;
    int m0 = blockIdx.x * 64;
    int n0 = blockIdx.y * 64;
    int kbase = blockIdx.z * KCHUNK;
    int tn = t & 15, tmg = t >> 4;

    unsigned long long acc[8][2];
#pragma unroll
    for (int i = 0; i < 8; i++) { acc[i][0] = 0ull; acc[i][1] = 0ull; }

    for (int kt = 0; kt < KCHUNK; kt += KT) {
        int k0 = kbase + kt;
        __syncthreads();
        // A tile: 64 rows x 16 k, two float4 per thread, stored duplicated
#pragma unroll
        for (int i = 0; i < 2; i++) {
            int idx = t + i * 128;
            int row = idx >> 2, cq = idx & 3;
            float4 av = *(const float4*)&g_Cp[(size_t)(m0 + row) * H_DIM + k0 + cq * 4];
            As2[cq * 4 + 0][row] = make_float2(av.x, av.x);
            As2[cq * 4 + 1][row] = make_float2(av.y, av.y);
            As2[cq * 4 + 2][row] = make_float2(av.z, av.z);
            As2[cq * 4 + 3][row] = make_float2(av.w, av.w);
        }
        // B tile: 16 k x 64 n, two float4 per thread
#pragma unroll
        for (int i = 0; i < 2; i++) {
            int idx = t + i * 128;
            int kk = idx >> 4, nq = idx & 15;
            *(float4*)&Bs[kk][nq * 4] =
                *(const float4*)&Bw[(size_t)(k0 + kk) * KIN + n0 + nq * 4];
        }
        __syncthreads();
#pragma unroll
        for (int kk = 0; kk < KT; kk++) {
            float4 bv = *(const float4*)&Bs[kk][tn * 4];     // LDS.128, conflict-free
            unsigned long long bp0 = pack2(bv.x, bv.y);
            unsigned long long bp1 = pack2(bv.z, bv.w);
#pragma unroll
            for (int i = 0; i < 8; i++) {
                unsigned long long a =
                    *(const unsigned long long*)&As2[kk][tmg * 8 + i];
                ffma2(acc[i][0], a, bp0);
                ffma2(acc[i][1], a, bp1);
            }
        }
    }
    float* out = g_Gpart[blockIdx.z];
#pragma unroll
    for (int i = 0; i < 8; i++) {
        int m = m0 + tmg * 8 + i;
        float4 r;
        r.x = f2lo(acc[i][0]); r.y = f2hi(acc[i][0]);
        r.z = f2lo(acc[i][1]); r.w = f2hi(acc[i][1]);
        *(float4*)&out[m * KIN + n0 + tn * 4] = r;
    }
}

// ---------------- kernel 3: deterministic split-K + y0 reduction (float4) ----------------
__global__ void reduceG_kernel() {
    int idx4 = blockIdx.x * blockDim.x + threadIdx.x;   // over float4s
    if (idx4 < Y_DIM * KIN / 4) {
        float4 s = make_float4(0.f, 0.f, 0.f, 0.f);
#pragma unroll
        for (int p = 0; p < SPLITS; p++) {
            float4 v = ((const float4*)g_Gpart[p])[idx4];
            s.x += v.x; s.y += v.y; s.z += v.z; s.w += v.w;
        }
        ((float4*)g_G)[idx4] = s;
    }
    if (idx4 < Y_DIM) {
        g_y0[idx4] = (g_y0p[idx4 * 4 + 0] + g_y0p[idx4 * 4 + 1]) +
                     (g_y0p[idx4 * 4 + 2] + g_y0p[idx4 * 4 + 3]);
    }
}

// ---------------- kernel 4: y = y0 + udu @ G^T ----------------
// 128 threads, tile 64(batch) x 64(y), per-thread 8x4. grid (4, 64) = 256 CTAs.
__global__ __launch_bounds__(128) void finalY_kernel(const float* __restrict__ u,
                                                     const float* __restrict__ du,
                                                     float* __restrict__ y) {
    __shared__ __align__(16) float2 As2[KT][66];  // duplicated udu [kk][b]
    __shared__ __align__(16) float  Bs[KT][64];   // G^T tile [kk][n]
    int t = threadIdx.x;
    int n0 = blockIdx.x * 64;
    int b0 = blockIdx.y * 64;
    int tn = t & 15, tmg = t >> 4;

    unsigned long long acc[8][2];
#pragma unroll
    for (int i = 0; i < 8; i++) { acc[i][0] = 0ull; acc[i][1] = 0ull; }

    for (int k0 = 0; k0 < KIN; k0 += KT) {
        __syncthreads();
        // A tile: 64 batch rows x 16 k (concat boundary 64 is KT-aligned)
#pragma unroll
        for (int i = 0; i < 2; i++) {
            int idx = t + i * 128;
            int row = idx >> 2, cq = idx & 3;
            float4 av;
            if (k0 < D_DIM)
                av = *(const float4*)&du[(size_t)(b0 + row) * D_DIM + k0 + cq * 4];
            else
                av = *(const float4*)&u[(size_t)(b0 + row) * U_DIM + (k0 - D_DIM) + cq * 4];
            As2[cq * 4 + 0][row] = make_float2(av.x, av.x);
            As2[cq * 4 + 1][row] = make_float2(av.y, av.y);
            As2[cq * 4 + 2][row] = make_float2(av.z, av.z);
            As2[cq * 4 + 3][row] = make_float2(av.w, av.w);
        }
        // B tile (transposed G): Bs[kk][n] = G[n0+n][k0+kk]
#pragma unroll
        for (int i = 0; i < 2; i++) {
            int idx = t + i * 128;
            int row = idx >> 2, cq = idx & 3;
            float4 gv = *(const float4*)&g_G[(n0 + row) * KIN + k0 + cq * 4];
            Bs[cq * 4 + 0][row] = gv.x;
            Bs[cq * 4 + 1][row] = gv.y;
            Bs[cq * 4 + 2][row] = gv.z;
            Bs[cq * 4 + 3][row] = gv.w;
        }
        __syncthreads();
#pragma unroll
        for (int kk = 0; kk < KT; kk++) {
            float4 bv = *(const float4*)&Bs[kk][tn * 4];     // LDS.128, conflict-free
            unsigned long long bp0 = pack2(bv.x, bv.y);
            unsigned long long bp1 = pack2(bv.z, bv.w);
#pragma unroll
            for (int i = 0; i < 8; i++) {
                unsigned long long a =
                    *(const unsigned long long*)&As2[kk][tmg * 8 + i];
                ffma2(acc[i][0], a, bp0);
                ffma2(acc[i][1], a, bp1);
            }
        }
    }
    float4 yv = *(const float4*)&g_y0[n0 + tn * 4];
#pragma unroll
    for (int i = 0; i < 8; i++) {
        int bb = b0 + tmg * 8 + i;
        float4 r;
        r.x = f2lo(acc[i][0]) + yv.x;
        r.y = f2hi(acc[i][0]) + yv.y;
        r.z = f2lo(acc[i][1]) + yv.z;
        r.w = f2hi(acc[i][1]) + yv.w;
        *(float4*)&y[(size_t)bb * Y_DIM + n0 + tn * 4] = r;
    }
}

// ---------------- launch ----------------
extern "C" void kernel_launch(void* const* d_in, const int* in_sizes, int n_in,
                              void* d_out, int out_size) {
    const float *u = nullptr, *du = nullptr, *h = nullptr, *om = nullptr,
                *Bw = nullptr, *Cw = nullptr;
    for (int i = 0; i < n_in; i++) {
        switch (in_sizes[i]) {
            case B_N * U_DIM:   u  = (const float*)d_in[i]; break;
            case B_N * D_DIM:   du = (const float*)d_in[i]; break;
            case H_DIM:         h  = (const float*)d_in[i]; break;
            case ORD:           om = (const float*)d_in[i]; break;
            case H_DIM * KIN:   Bw = (const float*)d_in[i]; break;
            case Y_DIM * H_DIM: Cw = (const float*)d_in[i]; break;
            default: break;
        }
    }
    if (!u || !du || !h || !om || !Bw || !Cw) {
        u  = (const float*)d_in[0];
        du = (const float*)d_in[1];
        h  = (const float*)d_in[2];
        om = (const float*)d_in[3];
        Bw = (const float*)d_in[4];
        Cw = (const float*)d_in[5];
    }
    float* y = (float*)d_out;

    coef_kernel<<<(ORD + 255) / 256, 256>>>(om, h);
    prep_kernel<<<dim3(4, Y_DIM), 256>>>(Cw);
    gemmG_kernel<<<dim3(Y_DIM / 64, KIN / 64, SPLITS), 128>>>(Bw);
    reduceG_kernel<<<(Y_DIM * KIN / 4 + 255) / 256, 256>>>();
    finalY_kernel<<<dim3(Y_DIM / 64, B_N / 64), 128>>>(u, du, y);
}

// round 6
// speedup vs baseline: 2.2279x; 1.5458x over previous
#include <cuda_runtime.h>
#include <cuda_bf16.h>
#include <cstdint>

// Problem dims
#define B_N    4096
#define U_DIM  256
#define D_DIM  64
#define KIN    320
#define H_DIM  8192
#define ORD    4096
#define Y_DIM  256
#define DELTA_F 0.1f

#define GSPLITS 16
#define KCHUNK  512     // H_DIM / GSPLITS

// ---------------- scratch (static device globals) ----------------
__device__ uint4 g_Chi4[Y_DIM * H_DIM / 8];   // C' hi bf16 [256][8192]
__device__ uint4 g_Clo4[Y_DIM * H_DIM / 8];
__device__ uint4 g_BwTh4[KIN * H_DIM / 8];    // Bw^T hi bf16 [320][8192]
__device__ uint4 g_BwTl4[KIN * H_DIM / 8];
__device__ uint4 g_uduh4[B_N * KIN / 8];      // [du|u] hi bf16 [4096][320]
__device__ uint4 g_udul4[B_N * KIN / 8];
__device__ float g_Gpart[GSPLITS][Y_DIM * KIN];
__device__ uint4 g_Ghi4[Y_DIM * KIN / 8];     // G hi bf16 [256][320]
__device__ uint4 g_Glo4[Y_DIM * KIN / 8];
__device__ float g_p[ORD], g_q[ORD], g_rec[H_DIM];
__device__ float g_y0p[Y_DIM * 4], g_y0[Y_DIM];

// ---------------- helpers ----------------
__device__ __forceinline__ uint32_t smem_u32(const void* p) {
    uint32_t a;
    asm("{ .reg .u64 t; cvta.to.shared.u64 t, %1; cvt.u32.u64 %0, t; }"
        : "=r"(a) : "l"(p));
    return a;
}
#define SW128(o) ((o) ^ (((o) >> 3) & 0x70))

__device__ __forceinline__ void ldsm_x4(uint32_t* r, uint32_t addr) {
    asm volatile("ldmatrix.sync.aligned.m8n8.x4.shared.b16 {%0,%1,%2,%3}, [%4];"
                 : "=r"(r[0]), "=r"(r[1]), "=r"(r[2]), "=r"(r[3]) : "r"(addr));
}
__device__ __forceinline__ void mma16816(float* c, const uint32_t* a, const uint32_t* b) {
    asm volatile(
        "mma.sync.aligned.m16n8k16.row.col.f32.bf16.bf16.f32 "
        "{%0,%1,%2,%3}, {%4,%5,%6,%7}, {%8,%9}, {%0,%1,%2,%3};"
        : "+f"(c[0]), "+f"(c[1]), "+f"(c[2]), "+f"(c[3])
        : "r"(a[0]), "r"(a[1]), "r"(a[2]), "r"(a[3]), "r"(b[0]), "r"(b[1]));
}

__device__ __forceinline__ void split1(float v, unsigned short& h, unsigned short& l) {
    __nv_bfloat16 hb = __float2bfloat16(v);
    float r = v - __bfloat162float(hb);
    __nv_bfloat16 lb = __float2bfloat16(r);
    h = *reinterpret_cast<unsigned short*>(&hb);
    l = *reinterpret_cast<unsigned short*>(&lb);
}
__device__ __forceinline__ uint32_t pkw(unsigned short a, unsigned short b) {
    return (uint32_t)a | ((uint32_t)b << 16);
}

// ---------------- kernel 0: rotation coefficients ----------------
__global__ void coef_kernel(const float* __restrict__ om, const float* __restrict__ h) {
    int j = blockIdx.x * blockDim.x + threadIdx.x;
    if (j >= ORD) return;
    float w = om[j];
    float s, c;
    sincosf(w * DELTA_F, &s, &c);
    float inv = 1.0f / w;
    g_p[j] = s * inv;
    g_q[j] = (c - 1.0f) * inv;
    float h0 = h[2 * j], h1 = h[2 * j + 1];
    g_rec[2 * j]     =  c * h0 + s * h1;
    g_rec[2 * j + 1] = -s * h0 + c * h1;
}

// ---------------- kernel 1: C' fold -> bf16 hi/lo + y0 partials ----------------
__global__ __launch_bounds__(256) void prep_kernel(const float* __restrict__ Cw) {
    int m = blockIdx.y;
    int jb = blockIdx.x * 1024 + threadIdx.x * 4;     // 4 pairs = 8 elems
    const float* crow = Cw + (size_t)m * H_DIM;
    float4 c0 = *(const float4*)(crow + 2 * jb);
    float4 c1 = *(const float4*)(crow + 2 * jb + 4);
    float4 pv = *(const float4*)(g_p + jb);
    float4 qv = *(const float4*)(g_q + jb);
    float4 r0 = *(const float4*)(g_rec + 2 * jb);
    float4 r1 = *(const float4*)(g_rec + 2 * jb + 4);
    float y0acc = c0.x * r0.x + c0.y * r0.y + c0.z * r0.z + c0.w * r0.w +
                  c1.x * r1.x + c1.y * r1.y + c1.z * r1.z + c1.w * r1.w;
    float o[8];
    o[0] =  c0.x * pv.x + c0.y * qv.x;  o[1] = -c0.x * qv.x + c0.y * pv.x;
    o[2] =  c0.z * pv.y + c0.w * qv.y;  o[3] = -c0.z * qv.y + c0.w * pv.y;
    o[4] =  c1.x * pv.z + c1.y * qv.z;  o[5] = -c1.x * qv.z + c1.y * pv.z;
    o[6] =  c1.z * pv.w + c1.w * qv.w;  o[7] = -c1.z * qv.w + c1.w * pv.w;
    unsigned short h[8], l[8];
#pragma unroll
    for (int i = 0; i < 8; i++) split1(o[i], h[i], l[i]);
    size_t vi = ((size_t)m * H_DIM + 2 * jb) / 8;
    g_Chi4[vi] = make_uint4(pkw(h[0], h[1]), pkw(h[2], h[3]), pkw(h[4], h[5]), pkw(h[6], h[7]));
    g_Clo4[vi] = make_uint4(pkw(l[0], l[1]), pkw(l[2], l[3]), pkw(l[4], l[5]), pkw(l[6], l[7]));
    __shared__ float red[256];
    red[threadIdx.x] = y0acc;
    __syncthreads();
    for (int off = 128; off > 0; off >>= 1) {
        if (threadIdx.x < off) red[threadIdx.x] += red[threadIdx.x + off];
        __syncthreads();
    }
    if (threadIdx.x == 0) g_y0p[m * 4 + blockIdx.x] = red[0];
}

// ---------------- kernel 2: Bw transpose + split -> BwT hi/lo [n][k] ----------------
__global__ __launch_bounds__(256) void bwsplit_kernel(const float* __restrict__ Bw) {
    __shared__ float tile[64][65];
    int k0 = blockIdx.x * 64, n0 = blockIdx.y * 64, t = threadIdx.x;
#pragma unroll
    for (int i = 0; i < 4; i++) {
        int idx = t + i * 256;
        int r = idx >> 4, c4 = idx & 15;
        float4 v = *(const float4*)&Bw[(size_t)(k0 + r) * KIN + n0 + c4 * 4];
        // scalar stores: row stride 65 floats is not 16B-aligned for odd rows
        tile[r][c4 * 4 + 0] = v.x;
        tile[r][c4 * 4 + 1] = v.y;
        tile[r][c4 * 4 + 2] = v.z;
        tile[r][c4 * 4 + 3] = v.w;
    }
    __syncthreads();
#pragma unroll
    for (int i = 0; i < 2; i++) {
        int idx = t + i * 256;
        int nr = idx >> 3, q = idx & 7;
        unsigned short h[8], l[8];
#pragma unroll
        for (int e = 0; e < 8; e++) split1(tile[q * 8 + e][nr], h[e], l[e]);
        size_t vi = ((size_t)(n0 + nr) * H_DIM + k0 + q * 8) / 8;
        g_BwTh4[vi] = make_uint4(pkw(h[0], h[1]), pkw(h[2], h[3]), pkw(h[4], h[5]), pkw(h[6], h[7]));
        g_BwTl4[vi] = make_uint4(pkw(l[0], l[1]), pkw(l[2], l[3]), pkw(l[4], l[5]), pkw(l[6], l[7]));
    }
}

// ---------------- kernel 3: udu concat + split ----------------
__global__ __launch_bounds__(256) void udusplit_kernel(const float* __restrict__ u,
                                                       const float* __restrict__ du) {
    int idx4 = blockIdx.x * blockDim.x + threadIdx.x;   // one float4 each
    if (idx4 >= B_N * KIN / 4) return;
    int row = idx4 / 80;
    int col = (idx4 % 80) * 4;
    float4 v;
    if (col < D_DIM) v = *(const float4*)&du[(size_t)row * D_DIM + col];
    else             v = *(const float4*)&u[(size_t)row * U_DIM + col - D_DIM];
    unsigned short h[4], l[4];
    split1(v.x, h[0], l[0]); split1(v.y, h[1], l[1]);
    split1(v.z, h[2], l[2]); split1(v.w, h[3], l[3]);
    size_t vi = ((size_t)row * KIN + col) / 4;
    ((uint2*)g_uduh4)[vi] = make_uint2(pkw(h[0], h[1]), pkw(h[2], h[3]));
    ((uint2*)g_udul4)[vi] = make_uint2(pkw(l[0], l[1]), pkw(l[2], l[3]));
}

// ---------------- mma tile core (shared by both GEMMs) ----------------
// smem layout: Ah [0,16K) Al [16K,32K) Bh [32K,40K) Bl [40K,48K)
#define SM_AH 0
#define SM_AL 16384
#define SM_BH 32768
#define SM_BL 40960

struct MmaCtx {
    uint32_t sbase;
    int lane, wm, wn;
    float acc[2][4][4];
};

__device__ __forceinline__ void mma_terms(MmaCtx& cx) {
    const int AOFF[3] = {SM_AH, SM_AH, SM_AL};
    const int BOFF[3] = {SM_BH, SM_BL, SM_BH};
#pragma unroll
    for (int term = 0; term < 3; term++) {
        uint32_t ab = cx.sbase + AOFF[term];
        uint32_t bb = cx.sbase + BOFF[term];
#pragma unroll
        for (int s = 0; s < 4; s++) {
            uint32_t af[2][4], bf[2][4];
#pragma unroll
            for (int mt = 0; mt < 2; mt++) {
                int row = cx.wm * 32 + mt * 16 + (cx.lane & 15);
                int cb = s * 32 + ((cx.lane >> 4) << 4);
                ldsm_x4(af[mt], ab + SW128((uint32_t)(row * 128 + cb)));
            }
#pragma unroll
            for (int nh = 0; nh < 2; nh++) {
                // B fragment, [n][k] smem: NON-trans ldmatrix.
                // lanes 0-7: n 0-7 k-blk0; 8-15: n 0-7 k-blk1; 16-23: n+8 k0; 24-31: n+8 k1
                int row = cx.wn * 32 + nh * 16 + (cx.lane & 7) + ((cx.lane & 16) ? 8 : 0);
                int cb = s * 32 + ((cx.lane & 8) ? 16 : 0);
                ldsm_x4(bf[nh], bb + SW128((uint32_t)(row * 128 + cb)));
            }
#pragma unroll
            for (int mt = 0; mt < 2; mt++)
#pragma unroll
                for (int nt = 0; nt < 4; nt++)
                    mma16816(cx.acc[mt][nt], af[mt], &bf[nt >> 1][(nt & 1) * 2]);
        }
    }
}

// ---------------- kernel 4: gemmG = C' @ BwT^T via HMMA, split-K ----------------
// grid (5 n, 2 m, GSPLITS), 256 threads = 4x2 warps, CTA tile 128x64
__global__ __launch_bounds__(256) void gemmG_kernel() {
    __shared__ __align__(128) char sm[49152];
    MmaCtx cx;
    cx.sbase = smem_u32(sm);
    int t = threadIdx.x;
    cx.lane = t & 31;
    int w = t >> 5;
    cx.wm = w >> 1; cx.wn = w & 1;
    int n0 = blockIdx.x * 64, m0 = blockIdx.y * 128, sp = blockIdx.z;
#pragma unroll
    for (int mt = 0; mt < 2; mt++)
#pragma unroll
        for (int nt = 0; nt < 4; nt++)
#pragma unroll
            for (int e = 0; e < 4; e++) cx.acc[mt][nt][e] = 0.0f;

    for (int kt = 0; kt < KCHUNK / 64; kt++) {
        int ktg = sp * (KCHUNK / 64) + kt;
        __syncthreads();
        // A: 128 rows x 8 chunks (hi+lo)
#pragma unroll
        for (int i = 0; i < 4; i++) {
            int idx = t + i * 256;
            int row = idx >> 3, q = idx & 7;
            uint32_t off = SW128((uint32_t)(row * 128 + q * 16));
            size_t src = (size_t)(m0 + row) * (H_DIM / 8) + ktg * 8 + q;
            *(uint4*)(sm + SM_AH + off) = g_Chi4[src];
            *(uint4*)(sm + SM_AL + off) = g_Clo4[src];
        }
        // B: 64 rows x 8 chunks (hi+lo)
#pragma unroll
        for (int i = 0; i < 2; i++) {
            int idx = t + i * 256;
            int row = idx >> 3, q = idx & 7;
            uint32_t off = SW128((uint32_t)(row * 128 + q * 16));
            size_t src = (size_t)(n0 + row) * (H_DIM / 8) + ktg * 8 + q;
            *(uint4*)(sm + SM_BH + off) = g_BwTh4[src];
            *(uint4*)(sm + SM_BL + off) = g_BwTl4[src];
        }
        __syncthreads();
        mma_terms(cx);
    }
    float* out = g_Gpart[sp];
    int gid = cx.lane >> 2, tig = cx.lane & 3;
#pragma unroll
    for (int mt = 0; mt < 2; mt++)
#pragma unroll
        for (int nt = 0; nt < 4; nt++) {
            int r0 = m0 + cx.wm * 32 + mt * 16 + gid;
            int c = n0 + cx.wn * 32 + nt * 8 + tig * 2;
            *(float2*)&out[(size_t)r0 * KIN + c] =
                make_float2(cx.acc[mt][nt][0], cx.acc[mt][nt][1]);
            *(float2*)&out[(size_t)(r0 + 8) * KIN + c] =
                make_float2(cx.acc[mt][nt][2], cx.acc[mt][nt][3]);
        }
}

// ---------------- kernel 5: split-K reduce -> G bf16 hi/lo + y0 ----------------
__global__ void reduceG_kernel() {
    int idx = blockIdx.x * blockDim.x + threadIdx.x;
    if (idx < Y_DIM * KIN) {
        float s = 0.0f;
#pragma unroll
        for (int p = 0; p < GSPLITS; p++) s += g_Gpart[p][idx];
        unsigned short h, l;
        split1(s, h, l);
        ((unsigned short*)g_Ghi4)[idx] = h;
        ((unsigned short*)g_Glo4)[idx] = l;
    }
    if (idx < Y_DIM) {
        g_y0[idx] = (g_y0p[idx * 4 + 0] + g_y0p[idx * 4 + 1]) +
                    (g_y0p[idx * 4 + 2] + g_y0p[idx * 4 + 3]);
    }
}

// ---------------- kernel 6: finalY = y0 + udu @ G^T via HMMA ----------------
// grid (4 n, 32 m), 256 threads, CTA tile 128x64, K = 320 (5 tiles)
__global__ __launch_bounds__(256) void finalY_kernel(float* __restrict__ y) {
    __shared__ __align__(128) char sm[49152];
    MmaCtx cx;
    cx.sbase = smem_u32(sm);
    int t = threadIdx.x;
    cx.lane = t & 31;
    int w = t >> 5;
    cx.wm = w >> 1; cx.wn = w & 1;
    int n0 = blockIdx.x * 64, m0 = blockIdx.y * 128;
#pragma unroll
    for (int mt = 0; mt < 2; mt++)
#pragma unroll
        for (int nt = 0; nt < 4; nt++)
#pragma unroll
            for (int e = 0; e < 4; e++) cx.acc[mt][nt][e] = 0.0f;

#pragma unroll 1
    for (int kt = 0; kt < KIN / 64; kt++) {
        __syncthreads();
#pragma unroll
        for (int i = 0; i < 4; i++) {
            int idx = t + i * 256;
            int row = idx >> 3, q = idx & 7;
            uint32_t off = SW128((uint32_t)(row * 128 + q * 16));
            size_t src = (size_t)(m0 + row) * (KIN / 8) + kt * 8 + q;
            *(uint4*)(sm + SM_AH + off) = g_uduh4[src];
            *(uint4*)(sm + SM_AL + off) = g_udul4[src];
        }
#pragma unroll
        for (int i = 0; i < 2; i++) {
            int idx = t + i * 256;
            int row = idx >> 3, q = idx & 7;
            uint32_t off = SW128((uint32_t)(row * 128 + q * 16));
            size_t src = (size_t)(n0 + row) * (KIN / 8) + kt * 8 + q;
            *(uint4*)(sm + SM_BH + off) = g_Ghi4[src];
            *(uint4*)(sm + SM_BL + off) = g_Glo4[src];
        }
        __syncthreads();
        mma_terms(cx);
    }
    int gid = cx.lane >> 2, tig = cx.lane & 3;
#pragma unroll
    for (int mt = 0; mt < 2; mt++)
#pragma unroll
        for (int nt = 0; nt < 4; nt++) {
            int r0 = m0 + cx.wm * 32 + mt * 16 + gid;
            int c = n0 + cx.wn * 32 + nt * 8 + tig * 2;
            float2 y0v = *(const float2*)&g_y0[c];
            *(float2*)&y[(size_t)r0 * Y_DIM + c] =
                make_float2(cx.acc[mt][nt][0] + y0v.x, cx.acc[mt][nt][1] + y0v.y);
            *(float2*)&y[(size_t)(r0 + 8) * Y_DIM + c] =
                make_float2(cx.acc[mt][nt][2] + y0v.x, cx.acc[mt][nt][3] + y0v.y);
        }
}

// ---------------- launch ----------------
extern "C" void kernel_launch(void* const* d_in, const int* in_sizes, int n_in,
                              void* d_out, int out_size) {
    const float *u = nullptr, *du = nullptr, *h = nullptr, *om = nullptr,
                *Bw = nullptr, *Cw = nullptr;
    for (int i = 0; i < n_in; i++) {
        switch (in_sizes[i]) {
            case B_N * U_DIM:   u  = (const float*)d_in[i]; break;
            case B_N * D_DIM:   du = (const float*)d_in[i]; break;
            case H_DIM:         h  = (const float*)d_in[i]; break;
            case ORD:           om = (const float*)d_in[i]; break;
            case H_DIM * KIN:   Bw = (const float*)d_in[i]; break;
            case Y_DIM * H_DIM: Cw = (const float*)d_in[i]; break;
            default: break;
        }
    }
    if (!u || !du || !h || !om || !Bw || !Cw) {
        u  = (const float*)d_in[0];
        du = (const float*)d_in[1];
        h  = (const float*)d_in[2];
        om = (const float*)d_in[3];
        Bw = (const float*)d_in[4];
        Cw = (const float*)d_in[5];
    }
    float* y = (float*)d_out;

    coef_kernel<<<ORD / 256, 256>>>(om, h);
    prep_kernel<<<dim3(4, Y_DIM), 256>>>(Cw);
    bwsplit_kernel<<<dim3(H_DIM / 64, KIN / 64), 256>>>(Bw);
    udusplit_kernel<<<(B_N * KIN / 4) / 256, 256>>>(u, du);
    gemmG_kernel<<<dim3(KIN / 64, Y_DIM / 128, GSPLITS), 256>>>();
    reduceG_kernel<<<(Y_DIM * KIN + 255) / 256, 256>>>();
    finalY_kernel<<<dim3(Y_DIM / 64, B_N / 128), 256>>>(y);
}

// round 7
// speedup vs baseline: 2.4005x; 1.0775x over previous
#include <cuda_runtime.h>
#include <cuda_bf16.h>
#include <cstdint>

// Problem dims
#define B_N    4096
#define U_DIM  256
#define D_DIM  64
#define KIN    320
#define H_DIM  8192
#define ORD    4096
#define Y_DIM  256
#define DELTA_F 0.1f

#define GSPLITS 32
#define KCHUNK  256     // H_DIM / GSPLITS

// ---------------- scratch (static device globals) ----------------
__device__ uint4 g_Chi4[Y_DIM * H_DIM / 8];   // C' hi bf16 [256][8192]
__device__ uint4 g_Clo4[Y_DIM * H_DIM / 8];
__device__ uint4 g_BwTh4[KIN * H_DIM / 8];    // Bw^T hi bf16 [320][8192]
__device__ uint4 g_BwTl4[KIN * H_DIM / 8];
__device__ float g_Gpart[GSPLITS][Y_DIM * KIN];
__device__ uint4 g_Ghi4[Y_DIM * KIN / 8];     // G hi bf16 [256][320]
__device__ uint4 g_Glo4[Y_DIM * KIN / 8];
__device__ float g_p[ORD], g_q[ORD], g_rec[H_DIM];
__device__ float g_y0p[Y_DIM * 4], g_y0[Y_DIM];

// ---------------- helpers ----------------
__device__ __forceinline__ uint32_t smem_u32(const void* p) {
    uint32_t a;
    asm("{ .reg .u64 t; cvta.to.shared.u64 t, %1; cvt.u32.u64 %0, t; }"
        : "=r"(a) : "l"(p));
    return a;
}
#define SW128(o) ((o) ^ (((o) >> 3) & 0x70))

__device__ __forceinline__ void ldsm_x4(uint32_t* r, uint32_t addr) {
    asm volatile("ldmatrix.sync.aligned.m8n8.x4.shared.b16 {%0,%1,%2,%3}, [%4];"
                 : "=r"(r[0]), "=r"(r[1]), "=r"(r[2]), "=r"(r[3]) : "r"(addr));
}
__device__ __forceinline__ void mma16816(float* c, const uint32_t* a, const uint32_t* b) {
    asm volatile(
        "mma.sync.aligned.m16n8k16.row.col.f32.bf16.bf16.f32 "
        "{%0,%1,%2,%3}, {%4,%5,%6,%7}, {%8,%9}, {%0,%1,%2,%3};"
        : "+f"(c[0]), "+f"(c[1]), "+f"(c[2]), "+f"(c[3])
        : "r"(a[0]), "r"(a[1]), "r"(a[2]), "r"(a[3]), "r"(b[0]), "r"(b[1]));
}

__device__ __forceinline__ void split1(float v, unsigned short& h, unsigned short& l) {
    __nv_bfloat16 hb = __float2bfloat16(v);
    float r = v - __bfloat162float(hb);
    __nv_bfloat16 lb = __float2bfloat16(r);
    h = *reinterpret_cast<unsigned short*>(&hb);
    l = *reinterpret_cast<unsigned short*>(&lb);
}
__device__ __forceinline__ uint32_t pkw(unsigned short a, unsigned short b) {
    return (uint32_t)a | ((uint32_t)b << 16);
}

// ---------------- kernel 0: rotation coefficients ----------------
__global__ void coef_kernel(const float* __restrict__ om, const float* __restrict__ h) {
    int j = blockIdx.x * blockDim.x + threadIdx.x;
    if (j >= ORD) return;
    float w = om[j];
    float s, c;
    sincosf(w * DELTA_F, &s, &c);
    float inv = 1.0f / w;
    g_p[j] = s * inv;
    g_q[j] = (c - 1.0f) * inv;
    float h0 = h[2 * j], h1 = h[2 * j + 1];
    g_rec[2 * j]     =  c * h0 + s * h1;
    g_rec[2 * j + 1] = -s * h0 + c * h1;
}

// ---------------- kernel 1: C' fold -> bf16 hi/lo + y0 partials ----------------
__global__ __launch_bounds__(256) void prep_kernel(const float* __restrict__ Cw) {
    int m = blockIdx.y;
    int jb = blockIdx.x * 1024 + threadIdx.x * 4;     // 4 pairs = 8 elems
    const float* crow = Cw + (size_t)m * H_DIM;
    float4 c0 = *(const float4*)(crow + 2 * jb);
    float4 c1 = *(const float4*)(crow + 2 * jb + 4);
    float4 pv = *(const float4*)(g_p + jb);
    float4 qv = *(const float4*)(g_q + jb);
    float4 r0 = *(const float4*)(g_rec + 2 * jb);
    float4 r1 = *(const float4*)(g_rec + 2 * jb + 4);
    float y0acc = c0.x * r0.x + c0.y * r0.y + c0.z * r0.z + c0.w * r0.w +
                  c1.x * r1.x + c1.y * r1.y + c1.z * r1.z + c1.w * r1.w;
    float o[8];
    o[0] =  c0.x * pv.x + c0.y * qv.x;  o[1] = -c0.x * qv.x + c0.y * pv.x;
    o[2] =  c0.z * pv.y + c0.w * qv.y;  o[3] = -c0.z * qv.y + c0.w * pv.y;
    o[4] =  c1.x * pv.z + c1.y * qv.z;  o[5] = -c1.x * qv.z + c1.y * pv.z;
    o[6] =  c1.z * pv.w + c1.w * qv.w;  o[7] = -c1.z * qv.w + c1.w * pv.w;
    unsigned short h[8], l[8];
#pragma unroll
    for (int i = 0; i < 8; i++) split1(o[i], h[i], l[i]);
    size_t vi = ((size_t)m * H_DIM + 2 * jb) / 8;
    g_Chi4[vi] = make_uint4(pkw(h[0], h[1]), pkw(h[2], h[3]), pkw(h[4], h[5]), pkw(h[6], h[7]));
    g_Clo4[vi] = make_uint4(pkw(l[0], l[1]), pkw(l[2], l[3]), pkw(l[4], l[5]), pkw(l[6], l[7]));
    __shared__ float red[256];
    red[threadIdx.x] = y0acc;
    __syncthreads();
    for (int off = 128; off > 0; off >>= 1) {
        if (threadIdx.x < off) red[threadIdx.x] += red[threadIdx.x + off];
        __syncthreads();
    }
    if (threadIdx.x == 0) g_y0p[m * 4 + blockIdx.x] = red[0];
}

// ---------------- kernel 2: Bw transpose + split -> BwT hi/lo [n][k] ----------------
__global__ __launch_bounds__(256) void bwsplit_kernel(const float* __restrict__ Bw) {
    __shared__ float tile[64][65];
    int k0 = blockIdx.x * 64, n0 = blockIdx.y * 64, t = threadIdx.x;
#pragma unroll
    for (int i = 0; i < 4; i++) {
        int idx = t + i * 256;
        int r = idx >> 4, c4 = idx & 15;
        float4 v = *(const float4*)&Bw[(size_t)(k0 + r) * KIN + n0 + c4 * 4];
        tile[r][c4 * 4 + 0] = v.x;
        tile[r][c4 * 4 + 1] = v.y;
        tile[r][c4 * 4 + 2] = v.z;
        tile[r][c4 * 4 + 3] = v.w;
    }
    __syncthreads();
#pragma unroll
    for (int i = 0; i < 2; i++) {
        int idx = t + i * 256;
        int nr = idx >> 3, q = idx & 7;
        unsigned short h[8], l[8];
#pragma unroll
        for (int e = 0; e < 8; e++) split1(tile[q * 8 + e][nr], h[e], l[e]);
        size_t vi = ((size_t)(n0 + nr) * H_DIM + k0 + q * 8) / 8;
        g_BwTh4[vi] = make_uint4(pkw(h[0], h[1]), pkw(h[2], h[3]), pkw(h[4], h[5]), pkw(h[6], h[7]));
        g_BwTl4[vi] = make_uint4(pkw(l[0], l[1]), pkw(l[2], l[3]), pkw(l[4], l[5]), pkw(l[6], l[7]));
    }
}

// ---------------- mma fragment core ----------------
struct MmaCtx {
    int lane, wm, wn;
    float acc[2][4][4];
};

__device__ __forceinline__ void mma_terms(MmaCtx& cx, uint32_t ah, uint32_t al,
                                          uint32_t bh, uint32_t bl) {
    uint32_t AB[3] = {ah, ah, al};
    uint32_t BB[3] = {bh, bl, bh};
#pragma unroll
    for (int term = 0; term < 3; term++) {
        uint32_t ab = AB[term], bb = BB[term];
#pragma unroll
        for (int s = 0; s < 4; s++) {
            uint32_t af[2][4], bf[2][4];
#pragma unroll
            for (int mt = 0; mt < 2; mt++) {
                int row = cx.wm * 32 + mt * 16 + (cx.lane & 15);
                int cb = s * 32 + ((cx.lane >> 4) << 4);
                ldsm_x4(af[mt], ab + SW128((uint32_t)(row * 128 + cb)));
            }
#pragma unroll
            for (int nh = 0; nh < 2; nh++) {
                int row = cx.wn * 32 + nh * 16 + (cx.lane & 7) + ((cx.lane & 16) ? 8 : 0);
                int cb = s * 32 + ((cx.lane & 8) ? 16 : 0);
                ldsm_x4(bf[nh], bb + SW128((uint32_t)(row * 128 + cb)));
            }
#pragma unroll
            for (int mt = 0; mt < 2; mt++)
#pragma unroll
                for (int nt = 0; nt < 4; nt++)
                    mma16816(cx.acc[mt][nt], af[mt], &bf[nt >> 1][(nt & 1) * 2]);
        }
    }
}

// ---------------- kernel 3: gemmG = C' @ BwT^T via HMMA, split-K ----------------
// grid (5 n, 2 m, 32 splits) = 320 CTAs, 256 thr, CTA tile 128x64, 48KB smem (2 CTA/SM)
__global__ __launch_bounds__(256) void gemmG_kernel() {
    __shared__ __align__(128) char sm[49152];
    // layout: AH [0,16K) AL [16K,32K) BH [32K,40K) BL [40K,48K)
    uint32_t sb = smem_u32(sm);
    MmaCtx cx;
    int t = threadIdx.x;
    cx.lane = t & 31;
    int w = t >> 5;
    cx.wm = w >> 1; cx.wn = w & 1;
    int n0 = blockIdx.x * 64, m0 = blockIdx.y * 128, sp = blockIdx.z;
#pragma unroll
    for (int mt = 0; mt < 2; mt++)
#pragma unroll
        for (int nt = 0; nt < 4; nt++)
#pragma unroll
            for (int e = 0; e < 4; e++) cx.acc[mt][nt][e] = 0.0f;

    for (int kt = 0; kt < KCHUNK / 64; kt++) {
        int ktg = sp * (KCHUNK / 64) + kt;
        __syncthreads();
#pragma unroll
        for (int i = 0; i < 4; i++) {
            int idx = t + i * 256;
            int row = idx >> 3, q = idx & 7;
            uint32_t off = SW128((uint32_t)(row * 128 + q * 16));
            size_t src = (size_t)(m0 + row) * (H_DIM / 8) + ktg * 8 + q;
            *(uint4*)(sm + off)         = g_Chi4[src];
            *(uint4*)(sm + 16384 + off) = g_Clo4[src];
        }
#pragma unroll
        for (int i = 0; i < 2; i++) {
            int idx = t + i * 256;
            int row = idx >> 3, q = idx & 7;
            uint32_t off = SW128((uint32_t)(row * 128 + q * 16));
            size_t src = (size_t)(n0 + row) * (H_DIM / 8) + ktg * 8 + q;
            *(uint4*)(sm + 32768 + off) = g_BwTh4[src];
            *(uint4*)(sm + 40960 + off) = g_BwTl4[src];
        }
        __syncthreads();
        mma_terms(cx, sb, sb + 16384, sb + 32768, sb + 40960);
    }
    float* out = g_Gpart[sp];
    int gid = cx.lane >> 2, tig = cx.lane & 3;
#pragma unroll
    for (int mt = 0; mt < 2; mt++)
#pragma unroll
        for (int nt = 0; nt < 4; nt++) {
            int r0 = m0 + cx.wm * 32 + mt * 16 + gid;
            int c = n0 + cx.wn * 32 + nt * 8 + tig * 2;
            *(float2*)&out[(size_t)r0 * KIN + c] =
                make_float2(cx.acc[mt][nt][0], cx.acc[mt][nt][1]);
            *(float2*)&out[(size_t)(r0 + 8) * KIN + c] =
                make_float2(cx.acc[mt][nt][2], cx.acc[mt][nt][3]);
        }
}

// ---------------- kernel 4: split-K reduce -> G bf16 hi/lo + y0 ----------------
__global__ void reduceG_kernel() {
    int idx4 = blockIdx.x * blockDim.x + threadIdx.x;   // float4 granularity
    if (idx4 < Y_DIM * KIN / 4) {
        float4 s = make_float4(0.f, 0.f, 0.f, 0.f);
#pragma unroll
        for (int p = 0; p < GSPLITS; p++) {
            float4 v = *(const float4*)&g_Gpart[p][idx4 * 4];
            s.x += v.x; s.y += v.y; s.z += v.z; s.w += v.w;
        }
        unsigned short h[4], l[4];
        split1(s.x, h[0], l[0]); split1(s.y, h[1], l[1]);
        split1(s.z, h[2], l[2]); split1(s.w, h[3], l[3]);
        ((uint2*)g_Ghi4)[idx4] = make_uint2(pkw(h[0], h[1]), pkw(h[2], h[3]));
        ((uint2*)g_Glo4)[idx4] = make_uint2(pkw(l[0], l[1]), pkw(l[2], l[3]));
    }
    if (idx4 < Y_DIM) {
        g_y0[idx4] = (g_y0p[idx4 * 4 + 0] + g_y0p[idx4 * 4 + 1]) +
                     (g_y0p[idx4 * 4 + 2] + g_y0p[idx4 * 4 + 3]);
    }
}

// ---------------- kernel 5: finalY = y0 + udu @ G^T, A split on the fly ----------------
// grid (4 n, 64 m) = 256 CTAs, 128 thr, CTA tile 64x64, 32KB smem
__global__ __launch_bounds__(128) void finalY_kernel(const float* __restrict__ u,
                                                     const float* __restrict__ du,
                                                     float* __restrict__ y) {
    __shared__ __align__(128) char sm[32768];
    // layout: AH [0,8K) AL [8K,16K) BH [16K,24K) BL [24K,32K)
    uint32_t sb = smem_u32(sm);
    MmaCtx cx;
    int t = threadIdx.x;
    cx.lane = t & 31;
    int w = t >> 5;
    cx.wm = w >> 1; cx.wn = w & 1;
    int n0 = blockIdx.x * 64, m0 = blockIdx.y * 64;
#pragma unroll
    for (int mt = 0; mt < 2; mt++)
#pragma unroll
        for (int nt = 0; nt < 4; nt++)
#pragma unroll
            for (int e = 0; e < 4; e++) cx.acc[mt][nt][e] = 0.0f;

#pragma unroll 1
    for (int kt = 0; kt < KIN / 64; kt++) {
        __syncthreads();
        // A: 64 rows x 64 k, fp32 loaded + split in regs (du/u boundary is tile-aligned)
#pragma unroll
        for (int i = 0; i < 8; i++) {
            int idx = t + i * 128;
            int row = idx >> 4, q4 = idx & 15;    // q4*4 = k within tile
            float4 v;
            if (kt == 0)
                v = *(const float4*)&du[(size_t)(m0 + row) * D_DIM + q4 * 4];
            else
                v = *(const float4*)&u[(size_t)(m0 + row) * U_DIM + (kt - 1) * 64 + q4 * 4];
            unsigned short h[4], l[4];
            split1(v.x, h[0], l[0]); split1(v.y, h[1], l[1]);
            split1(v.z, h[2], l[2]); split1(v.w, h[3], l[3]);
            uint32_t off = SW128((uint32_t)(row * 128 + (q4 >> 1) * 16)) + (q4 & 1) * 8;
            *(uint2*)(sm + off)        = make_uint2(pkw(h[0], h[1]), pkw(h[2], h[3]));
            *(uint2*)(sm + 8192 + off) = make_uint2(pkw(l[0], l[1]), pkw(l[2], l[3]));
        }
        // B: 64 rows(n) x 64 k bf16 hi/lo from G
#pragma unroll
        for (int i = 0; i < 4; i++) {
            int idx = t + i * 128;
            int row = idx >> 3, q = idx & 7;
            uint32_t off = SW128((uint32_t)(row * 128 + q * 16));
            size_t src = (size_t)(n0 + row) * (KIN / 8) + kt * 8 + q;
            *(uint4*)(sm + 16384 + off) = g_Ghi4[src];
            *(uint4*)(sm + 24576 + off) = g_Glo4[src];
        }
        __syncthreads();
        mma_terms(cx, sb, sb + 8192, sb + 16384, sb + 24576);
    }
    int gid = cx.lane >> 2, tig = cx.lane & 3;
#pragma unroll
    for (int mt = 0; mt < 2; mt++)
#pragma unroll
        for (int nt = 0; nt < 4; nt++) {
            int r0 = m0 + cx.wm * 32 + mt * 16 + gid;
            int c = n0 + cx.wn * 32 + nt * 8 + tig * 2;
            float2 y0v = *(const float2*)&g_y0[c];
            *(float2*)&y[(size_t)r0 * Y_DIM + c] =
                make_float2(cx.acc[mt][nt][0] + y0v.x, cx.acc[mt][nt][1] + y0v.y);
            *(float2*)&y[(size_t)(r0 + 8) * Y_DIM + c] =
                make_float2(cx.acc[mt][nt][2] + y0v.x, cx.acc[mt][nt][3] + y0v.y);
        }
}

// ---------------- launch ----------------
extern "C" void kernel_launch(void* const* d_in, const int* in_sizes, int n_in,
                              void* d_out, int out_size) {
    const float *u = nullptr, *du = nullptr, *h = nullptr, *om = nullptr,
                *Bw = nullptr, *Cw = nullptr;
    for (int i = 0; i < n_in; i++) {
        switch (in_sizes[i]) {
            case B_N * U_DIM:   u  = (const float*)d_in[i]; break;
            case B_N * D_DIM:   du = (const float*)d_in[i]; break;
            case H_DIM:         h  = (const float*)d_in[i]; break;
            case ORD:           om = (const float*)d_in[i]; break;
            case H_DIM * KIN:   Bw = (const float*)d_in[i]; break;
            case Y_DIM * H_DIM: Cw = (const float*)d_in[i]; break;
            default: break;
        }
    }
    if (!u || !du || !h || !om || !Bw || !Cw) {
        u  = (const float*)d_in[0];
        du = (const float*)d_in[1];
        h  = (const float*)d_in[2];
        om = (const float*)d_in[3];
        Bw = (const float*)d_in[4];
        Cw = (const float*)d_in[5];
    }
    float* y = (float*)d_out;

    coef_kernel<<<ORD / 256, 256>>>(om, h);
    prep_kernel<<<dim3(4, Y_DIM), 256>>>(Cw);
    bwsplit_kernel<<<dim3(H_DIM / 64, KIN / 64), 256>>>(Bw);
    gemmG_kernel<<<dim3(KIN / 64, Y_DIM / 128, GSPLITS), 256>>>();
    reduceG_kernel<<<(Y_DIM * KIN / 4 + 255) / 256, 256>>>();
    finalY_kernel<<<dim3(Y_DIM / 64, B_N / 64), 128>>>(u, du, y);
}

// round 8
// speedup vs baseline: 2.7968x; 1.1651x over previous
#include <cuda_runtime.h>
#include <cuda_bf16.h>
#include <cstdint>

// Problem dims
#define B_N    4096
#define U_DIM  256
#define D_DIM  64
#define KIN    320
#define H_DIM  8192
#define ORD    4096
#define Y_DIM  256
#define DELTA_F 0.1f

#define GSPLITS 32
#define KCHUNK  256     // H_DIM / GSPLITS
#define STAGE_BYTES 49152

// ---------------- scratch (static device globals) ----------------
__device__ uint4 g_Chi4[Y_DIM * H_DIM / 8];   // C' hi bf16 [256][8192]
__device__ uint4 g_Clo4[Y_DIM * H_DIM / 8];
__device__ uint4 g_BwTh4[KIN * H_DIM / 8];    // Bw^T hi bf16 [320][8192]
__device__ uint4 g_BwTl4[KIN * H_DIM / 8];
__device__ float g_Gpart[GSPLITS][Y_DIM * KIN];
__device__ uint4 g_Ghi4[Y_DIM * KIN / 8];     // G hi bf16 [256][320]
__device__ uint4 g_Glo4[Y_DIM * KIN / 8];
__device__ float g_p[ORD], g_q[ORD], g_rec[H_DIM];
__device__ float g_y0p[Y_DIM * 4], g_y0[Y_DIM];

// ---------------- helpers ----------------
__device__ __forceinline__ uint32_t smem_u32(const void* p) {
    uint32_t a;
    asm("{ .reg .u64 t; cvta.to.shared.u64 t, %1; cvt.u32.u64 %0, t; }"
        : "=r"(a) : "l"(p));
    return a;
}
#define SW128(o) ((o) ^ (((o) >> 3) & 0x70))

__device__ __forceinline__ void ldsm_x4(uint32_t* r, uint32_t addr) {
    asm volatile("ldmatrix.sync.aligned.m8n8.x4.shared.b16 {%0,%1,%2,%3}, [%4];"
                 : "=r"(r[0]), "=r"(r[1]), "=r"(r[2]), "=r"(r[3]) : "r"(addr));
}
__device__ __forceinline__ void mma16816(float* c, const uint32_t* a, const uint32_t* b) {
    asm volatile(
        "mma.sync.aligned.m16n8k16.row.col.f32.bf16.bf16.f32 "
        "{%0,%1,%2,%3}, {%4,%5,%6,%7}, {%8,%9}, {%0,%1,%2,%3};"
        : "+f"(c[0]), "+f"(c[1]), "+f"(c[2]), "+f"(c[3])
        : "r"(a[0]), "r"(a[1]), "r"(a[2]), "r"(a[3]), "r"(b[0]), "r"(b[1]));
}
__device__ __forceinline__ void cpa16(uint32_t s, const void* g) {
    asm volatile("cp.async.cg.shared.global [%0], [%1], 16;" :: "r"(s), "l"(g) : "memory");
}
#define CPA_COMMIT() asm volatile("cp.async.commit_group;" ::: "memory")

__device__ __forceinline__ void split1(float v, unsigned short& h, unsigned short& l) {
    __nv_bfloat16 hb = __float2bfloat16(v);
    float r = v - __bfloat162float(hb);
    __nv_bfloat16 lb = __float2bfloat16(r);
    h = *reinterpret_cast<unsigned short*>(&hb);
    l = *reinterpret_cast<unsigned short*>(&lb);
}
__device__ __forceinline__ uint32_t pkw(unsigned short a, unsigned short b) {
    return (uint32_t)a | ((uint32_t)b << 16);
}

// ---------------- kernel 0: rotation coefficients ----------------
__global__ void coef_kernel(const float* __restrict__ om, const float* __restrict__ h) {
    int j = blockIdx.x * blockDim.x + threadIdx.x;
    if (j >= ORD) return;
    float w = om[j];
    float s, c;
    sincosf(w * DELTA_F, &s, &c);
    float inv = 1.0f / w;
    g_p[j] = s * inv;
    g_q[j] = (c - 1.0f) * inv;
    float h0 = h[2 * j], h1 = h[2 * j + 1];
    g_rec[2 * j]     =  c * h0 + s * h1;
    g_rec[2 * j + 1] = -s * h0 + c * h1;
}

// ---------------- kernel 1: C' fold -> bf16 hi/lo + y0 partials ----------------
__global__ __launch_bounds__(256) void prep_kernel(const float* __restrict__ Cw) {
    int m = blockIdx.y;
    int jb = blockIdx.x * 1024 + threadIdx.x * 4;
    const float* crow = Cw + (size_t)m * H_DIM;
    float4 c0 = *(const float4*)(crow + 2 * jb);
    float4 c1 = *(const float4*)(crow + 2 * jb + 4);
    float4 pv = *(const float4*)(g_p + jb);
    float4 qv = *(const float4*)(g_q + jb);
    float4 r0 = *(const float4*)(g_rec + 2 * jb);
    float4 r1 = *(const float4*)(g_rec + 2 * jb + 4);
    float y0acc = c0.x * r0.x + c0.y * r0.y + c0.z * r0.z + c0.w * r0.w +
                  c1.x * r1.x + c1.y * r1.y + c1.z * r1.z + c1.w * r1.w;
    float o[8];
    o[0] =  c0.x * pv.x + c0.y * qv.x;  o[1] = -c0.x * qv.x + c0.y * pv.x;
    o[2] =  c0.z * pv.y + c0.w * qv.y;  o[3] = -c0.z * qv.y + c0.w * pv.y;
    o[4] =  c1.x * pv.z + c1.y * qv.z;  o[5] = -c1.x * qv.z + c1.y * pv.z;
    o[6] =  c1.z * pv.w + c1.w * qv.w;  o[7] = -c1.z * qv.w + c1.w * pv.w;
    unsigned short h[8], l[8];
#pragma unroll
    for (int i = 0; i < 8; i++) split1(o[i], h[i], l[i]);
    size_t vi = ((size_t)m * H_DIM + 2 * jb) / 8;
    g_Chi4[vi] = make_uint4(pkw(h[0], h[1]), pkw(h[2], h[3]), pkw(h[4], h[5]), pkw(h[6], h[7]));
    g_Clo4[vi] = make_uint4(pkw(l[0], l[1]), pkw(l[2], l[3]), pkw(l[4], l[5]), pkw(l[6], l[7]));
    __shared__ float red[256];
    red[threadIdx.x] = y0acc;
    __syncthreads();
    for (int off = 128; off > 0; off >>= 1) {
        if (threadIdx.x < off) red[threadIdx.x] += red[threadIdx.x + off];
        __syncthreads();
    }
    if (threadIdx.x == 0) g_y0p[m * 4 + blockIdx.x] = red[0];
}

// ---------------- kernel 2: Bw transpose + split -> BwT hi/lo [n][k] ----------------
__global__ __launch_bounds__(256) void bwsplit_kernel(const float* __restrict__ Bw) {
    __shared__ float tile[64][65];
    int k0 = blockIdx.x * 64, n0 = blockIdx.y * 64, t = threadIdx.x;
#pragma unroll
    for (int i = 0; i < 4; i++) {
        int idx = t + i * 256;
        int r = idx >> 4, c4 = idx & 15;
        float4 v = *(const float4*)&Bw[(size_t)(k0 + r) * KIN + n0 + c4 * 4];
        tile[r][c4 * 4 + 0] = v.x;
        tile[r][c4 * 4 + 1] = v.y;
        tile[r][c4 * 4 + 2] = v.z;
        tile[r][c4 * 4 + 3] = v.w;
    }
    __syncthreads();
#pragma unroll
    for (int i = 0; i < 2; i++) {
        int idx = t + i * 256;
        int nr = idx >> 3, q = idx & 7;
        unsigned short h[8], l[8];
#pragma unroll
        for (int e = 0; e < 8; e++) split1(tile[q * 8 + e][nr], h[e], l[e]);
        size_t vi = ((size_t)(n0 + nr) * H_DIM + k0 + q * 8) / 8;
        g_BwTh4[vi] = make_uint4(pkw(h[0], h[1]), pkw(h[2], h[3]), pkw(h[4], h[5]), pkw(h[6], h[7]));
        g_BwTl4[vi] = make_uint4(pkw(l[0], l[1]), pkw(l[2], l[3]), pkw(l[4], l[5]), pkw(l[6], l[7]));
    }
}

// ---------------- mma fragment core ----------------
struct MmaCtx {
    int lane, wm, wn;
    float acc[2][4][4];
};

__device__ __forceinline__ void mma_terms(MmaCtx& cx, uint32_t ah, uint32_t al,
                                          uint32_t bh, uint32_t bl) {
    uint32_t AB[3] = {ah, ah, al};
    uint32_t BB[3] = {bh, bl, bh};
#pragma unroll
    for (int term = 0; term < 3; term++) {
        uint32_t ab = AB[term], bb = BB[term];
#pragma unroll
        for (int s = 0; s < 4; s++) {
            uint32_t af[2][4], bf[2][4];
#pragma unroll
            for (int mt = 0; mt < 2; mt++) {
                int row = cx.wm * 32 + mt * 16 + (cx.lane & 15);
                int cb = s * 32 + ((cx.lane >> 4) << 4);
                ldsm_x4(af[mt], ab + SW128((uint32_t)(row * 128 + cb)));
            }
#pragma unroll
            for (int nh = 0; nh < 2; nh++) {
                int row = cx.wn * 32 + nh * 16 + (cx.lane & 7) + ((cx.lane & 16) ? 8 : 0);
                int cb = s * 32 + ((cx.lane & 8) ? 16 : 0);
                ldsm_x4(bf[nh], bb + SW128((uint32_t)(row * 128 + cb)));
            }
#pragma unroll
            for (int mt = 0; mt < 2; mt++)
#pragma unroll
                for (int nt = 0; nt < 4; nt++)
                    mma16816(cx.acc[mt][nt], af[mt], &bf[nt >> 1][(nt & 1) * 2]);
        }
    }
}

// ---------------- gemmG tile prefetch (cp.async) ----------------
__device__ __forceinline__ void gemmG_load_stage(uint32_t sb, int t, int m0, int n0, int ktg) {
#pragma unroll
    for (int i = 0; i < 4; i++) {
        int idx = t + i * 256;
        int row = idx >> 3, q = idx & 7;
        uint32_t off = SW128((uint32_t)(row * 128 + q * 16));
        size_t src = (size_t)(m0 + row) * (H_DIM / 8) + ktg * 8 + q;
        cpa16(sb + off,         &g_Chi4[src]);
        cpa16(sb + 16384 + off, &g_Clo4[src]);
    }
#pragma unroll
    for (int i = 0; i < 2; i++) {
        int idx = t + i * 256;
        int row = idx >> 3, q = idx & 7;
        uint32_t off = SW128((uint32_t)(row * 128 + q * 16));
        size_t src = (size_t)(n0 + row) * (H_DIM / 8) + ktg * 8 + q;
        cpa16(sb + 32768 + off, &g_BwTh4[src]);
        cpa16(sb + 40960 + off, &g_BwTl4[src]);
    }
}

// ---------------- kernel 3: gemmG = C' @ BwT^T, 2-stage cp.async, 2 CTA/SM ----------------
// grid (5 n, 2 m, 32 splits) = 320 CTAs, 256 thr, CTA tile 128x64, 96KB dyn smem
__global__ __launch_bounds__(256, 2) void gemmG_kernel() {
    extern __shared__ __align__(128) char dsm[];
    uint32_t sb = smem_u32(dsm);
    MmaCtx cx;
    int t = threadIdx.x;
    cx.lane = t & 31;
    int w = t >> 5;
    cx.wm = w >> 1; cx.wn = w & 1;
    int n0 = blockIdx.x * 64, m0 = blockIdx.y * 128, sp = blockIdx.z;
    const int NT = KCHUNK / 64;           // 4 k-tiles per split
    int ktbase = sp * NT;
#pragma unroll
    for (int mt = 0; mt < 2; mt++)
#pragma unroll
        for (int nt = 0; nt < 4; nt++)
#pragma unroll
            for (int e = 0; e < 4; e++) cx.acc[mt][nt][e] = 0.0f;

    gemmG_load_stage(sb, t, m0, n0, ktbase);
    CPA_COMMIT();
#pragma unroll 1
    for (int kt = 0; kt < NT; kt++) {
        __syncthreads();   // protect stage (kt+1)&1 from overwrite while prior mma reads it
        if (kt + 1 < NT) {
            gemmG_load_stage(sb + ((kt + 1) & 1) * STAGE_BYTES, t, m0, n0, ktbase + kt + 1);
            CPA_COMMIT();
            asm volatile("cp.async.wait_group 1;" ::: "memory");
        } else {
            asm volatile("cp.async.wait_group 0;" ::: "memory");
        }
        __syncthreads();
        uint32_t ss = sb + (kt & 1) * STAGE_BYTES;
        mma_terms(cx, ss, ss + 16384, ss + 32768, ss + 40960);
    }
    float* out = g_Gpart[sp];
    int gid = cx.lane >> 2, tig = cx.lane & 3;
#pragma unroll
    for (int mt = 0; mt < 2; mt++)
#pragma unroll
        for (int nt = 0; nt < 4; nt++) {
            int r0 = m0 + cx.wm * 32 + mt * 16 + gid;
            int c = n0 + cx.wn * 32 + nt * 8 + tig * 2;
            *(float2*)&out[(size_t)r0 * KIN + c] =
                make_float2(cx.acc[mt][nt][0], cx.acc[mt][nt][1]);
            *(float2*)&out[(size_t)(r0 + 8) * KIN + c] =
                make_float2(cx.acc[mt][nt][2], cx.acc[mt][nt][3]);
        }
}

// ---------------- kernel 4: split-K reduce -> G bf16 hi/lo + y0 ----------------
__global__ void reduceG_kernel() {
    int idx4 = blockIdx.x * blockDim.x + threadIdx.x;
    if (idx4 < Y_DIM * KIN / 4) {
        float4 s = make_float4(0.f, 0.f, 0.f, 0.f);
#pragma unroll
        for (int p = 0; p < GSPLITS; p++) {
            float4 v = *(const float4*)&g_Gpart[p][idx4 * 4];
            s.x += v.x; s.y += v.y; s.z += v.z; s.w += v.w;
        }
        unsigned short h[4], l[4];
        split1(s.x, h[0], l[0]); split1(s.y, h[1], l[1]);
        split1(s.z, h[2], l[2]); split1(s.w, h[3], l[3]);
        ((uint2*)g_Ghi4)[idx4] = make_uint2(pkw(h[0], h[1]), pkw(h[2], h[3]));
        ((uint2*)g_Glo4)[idx4] = make_uint2(pkw(l[0], l[1]), pkw(l[2], l[3]));
    }
    if (idx4 < Y_DIM) {
        g_y0[idx4] = (g_y0p[idx4 * 4 + 0] + g_y0p[idx4 * 4 + 1]) +
                     (g_y0p[idx4 * 4 + 2] + g_y0p[idx4 * 4 + 3]);
    }
}

// ---------------- kernel 5: finalY = y0 + udu @ G^T, A split on the fly ----------------
// grid (4 n, 64 m) = 256 CTAs, 128 thr, CTA tile 64x64, 32KB smem
__global__ __launch_bounds__(128) void finalY_kernel(const float* __restrict__ u,
                                                     const float* __restrict__ du,
                                                     float* __restrict__ y) {
    __shared__ __align__(128) char sm[32768];
    uint32_t sb = smem_u32(sm);
    MmaCtx cx;
    int t = threadIdx.x;
    cx.lane = t & 31;
    int w = t >> 5;
    cx.wm = w >> 1; cx.wn = w & 1;
    int n0 = blockIdx.x * 64, m0 = blockIdx.y * 64;
#pragma unroll
    for (int mt = 0; mt < 2; mt++)
#pragma unroll
        for (int nt = 0; nt < 4; nt++)
#pragma unroll
            for (int e = 0; e < 4; e++) cx.acc[mt][nt][e] = 0.0f;

#pragma unroll 1
    for (int kt = 0; kt < KIN / 64; kt++) {
        __syncthreads();
#pragma unroll
        for (int i = 0; i < 8; i++) {
            int idx = t + i * 128;
            int row = idx >> 4, q4 = idx & 15;
            float4 v;
            if (kt == 0)
                v = *(const float4*)&du[(size_t)(m0 + row) * D_DIM + q4 * 4];
            else
                v = *(const float4*)&u[(size_t)(m0 + row) * U_DIM + (kt - 1) * 64 + q4 * 4];
            unsigned short h[4], l[4];
            split1(v.x, h[0], l[0]); split1(v.y, h[1], l[1]);
            split1(v.z, h[2], l[2]); split1(v.w, h[3], l[3]);
            uint32_t off = SW128((uint32_t)(row * 128 + (q4 >> 1) * 16)) + (q4 & 1) * 8;
            *(uint2*)(sm + off)        = make_uint2(pkw(h[0], h[1]), pkw(h[2], h[3]));
            *(uint2*)(sm + 8192 + off) = make_uint2(pkw(l[0], l[1]), pkw(l[2], l[3]));
        }
#pragma unroll
        for (int i = 0; i < 4; i++) {
            int idx = t + i * 128;
            int row = idx >> 3, q = idx & 7;
            uint32_t off = SW128((uint32_t)(row * 128 + q * 16));
            size_t src = (size_t)(n0 + row) * (KIN / 8) + kt * 8 + q;
            *(uint4*)(sm + 16384 + off) = g_Ghi4[src];
            *(uint4*)(sm + 24576 + off) = g_Glo4[src];
        }
        __syncthreads();
        mma_terms(cx, sb, sb + 8192, sb + 16384, sb + 24576);
    }
    int gid = cx.lane >> 2, tig = cx.lane & 3;
#pragma unroll
    for (int mt = 0; mt < 2; mt++)
#pragma unroll
        for (int nt = 0; nt < 4; nt++) {
            int r0 = m0 + cx.wm * 32 + mt * 16 + gid;
            int c = n0 + cx.wn * 32 + nt * 8 + tig * 2;
            float2 y0v = *(const float2*)&g_y0[c];
            *(float2*)&y[(size_t)r0 * Y_DIM + c] =
                make_float2(cx.acc[mt][nt][0] + y0v.x, cx.acc[mt][nt][1] + y0v.y);
            *(float2*)&y[(size_t)(r0 + 8) * Y_DIM + c] =
                make_float2(cx.acc[mt][nt][2] + y0v.x, cx.acc[mt][nt][3] + y0v.y);
        }
}

// ---------------- launch ----------------
extern "C" void kernel_launch(void* const* d_in, const int* in_sizes, int n_in,
                              void* d_out, int out_size) {
    const float *u = nullptr, *du = nullptr, *h = nullptr, *om = nullptr,
                *Bw = nullptr, *Cw = nullptr;
    for (int i = 0; i < n_in; i++) {
        switch (in_sizes[i]) {
            case B_N * U_DIM:   u  = (const float*)d_in[i]; break;
            case B_N * D_DIM:   du = (const float*)d_in[i]; break;
            case H_DIM:         h  = (const float*)d_in[i]; break;
            case ORD:           om = (const float*)d_in[i]; break;
            case H_DIM * KIN:   Bw = (const float*)d_in[i]; break;
            case Y_DIM * H_DIM: Cw = (const float*)d_in[i]; break;
            default: break;
        }
    }
    if (!u || !du || !h || !om || !Bw || !Cw) {
        u  = (const float*)d_in[0];
        du = (const float*)d_in[1];
        h  = (const float*)d_in[2];
        om = (const float*)d_in[3];
        Bw = (const float*)d_in[4];
        Cw = (const float*)d_in[5];
    }
    float* y = (float*)d_out;

    // idempotent, not a stream op — safe under graph capture, called every time
    cudaFuncSetAttribute(gemmG_kernel,
                         cudaFuncAttributeMaxDynamicSharedMemorySize, 2 * STAGE_BYTES);

    coef_kernel<<<ORD / 256, 256>>>(om, h);
    prep_kernel<<<dim3(4, Y_DIM), 256>>>(Cw);
    bwsplit_kernel<<<dim3(H_DIM / 64, KIN / 64), 256>>>(Bw);
    gemmG_kernel<<<dim3(KIN / 64, Y_DIM / 128, GSPLITS), 256, 2 * STAGE_BYTES>>>();
    reduceG_kernel<<<(Y_DIM * KIN / 4 + 255) / 256, 256>>>();
    finalY_kernel<<<dim3(Y_DIM / 64, B_N / 64), 128>>>(u, du, y);
}

// round 9
// speedup vs baseline: 2.9403x; 1.0513x over previous
#include <cuda_runtime.h>
#include <cuda_bf16.h>
#include <cstdint>

// Problem dims
#define B_N    4096
#define U_DIM  256
#define D_DIM  64
#define KIN    320
#define H_DIM  8192
#define ORD    4096
#define Y_DIM  256
#define DELTA_F 0.1f

#define GSPLITS 32
#define KCHUNK  256     // H_DIM / GSPLITS
#define STAGE_BYTES 49152

// ---------------- scratch (static device globals) ----------------
__device__ uint4 g_Chi4[Y_DIM * H_DIM / 8];   // C' hi bf16 [256][8192]
__device__ uint4 g_Clo4[Y_DIM * H_DIM / 8];
__device__ uint4 g_BwTh4[KIN * H_DIM / 8];    // Bw^T hi bf16 [320][8192]
__device__ uint4 g_BwTl4[KIN * H_DIM / 8];
__device__ float g_Gpart[GSPLITS][Y_DIM * KIN];
__device__ uint4 g_Ghi4[Y_DIM * KIN / 8];     // G hi bf16 [256][320]
__device__ uint4 g_Glo4[Y_DIM * KIN / 8];
__device__ float g_p[ORD], g_q[ORD], g_rec[H_DIM];
__device__ float g_y0p[Y_DIM * 4], g_y0[Y_DIM];

// ---------------- helpers ----------------
__device__ __forceinline__ uint32_t smem_u32(const void* p) {
    uint32_t a;
    asm("{ .reg .u64 t; cvta.to.shared.u64 t, %1; cvt.u32.u64 %0, t; }"
        : "=r"(a) : "l"(p));
    return a;
}
#define SW128(o) ((o) ^ (((o) >> 3) & 0x70))

__device__ __forceinline__ void ldsm_x4(uint32_t* r, uint32_t addr) {
    asm volatile("ldmatrix.sync.aligned.m8n8.x4.shared.b16 {%0,%1,%2,%3}, [%4];"
                 : "=r"(r[0]), "=r"(r[1]), "=r"(r[2]), "=r"(r[3]) : "r"(addr));
}
__device__ __forceinline__ void mma16816(float* c, const uint32_t* a, const uint32_t* b) {
    asm volatile(
        "mma.sync.aligned.m16n8k16.row.col.f32.bf16.bf16.f32 "
        "{%0,%1,%2,%3}, {%4,%5,%6,%7}, {%8,%9}, {%0,%1,%2,%3};"
        : "+f"(c[0]), "+f"(c[1]), "+f"(c[2]), "+f"(c[3])
        : "r"(a[0]), "r"(a[1]), "r"(a[2]), "r"(a[3]), "r"(b[0]), "r"(b[1]));
}
__device__ __forceinline__ void cpa16(uint32_t s, const void* g) {
    asm volatile("cp.async.cg.shared.global [%0], [%1], 16;" :: "r"(s), "l"(g) : "memory");
}
#define CPA_COMMIT() asm volatile("cp.async.commit_group;" ::: "memory")

__device__ __forceinline__ void split1(float v, unsigned short& h, unsigned short& l) {
    __nv_bfloat16 hb = __float2bfloat16(v);
    float r = v - __bfloat162float(hb);
    __nv_bfloat16 lb = __float2bfloat16(r);
    h = *reinterpret_cast<unsigned short*>(&hb);
    l = *reinterpret_cast<unsigned short*>(&lb);
}
__device__ __forceinline__ uint32_t pkw(unsigned short a, unsigned short b) {
    return (uint32_t)a | ((uint32_t)b << 16);
}

// ---------------- kernel 0: rotation coefficients ----------------
__global__ void coef_kernel(const float* __restrict__ om, const float* __restrict__ h) {
    int j = blockIdx.x * blockDim.x + threadIdx.x;
    if (j >= ORD) return;
    float w = om[j];
    float s, c;
    sincosf(w * DELTA_F, &s, &c);
    float inv = 1.0f / w;
    g_p[j] = s * inv;
    g_q[j] = (c - 1.0f) * inv;
    float h0 = h[2 * j], h1 = h[2 * j + 1];
    g_rec[2 * j]     =  c * h0 + s * h1;
    g_rec[2 * j + 1] = -s * h0 + c * h1;
}

// ---------------- kernel 1: C' fold -> bf16 hi/lo + y0 partials ----------------
__global__ __launch_bounds__(256) void prep_kernel(const float* __restrict__ Cw) {
    int m = blockIdx.y;
    int jb = blockIdx.x * 1024 + threadIdx.x * 4;
    const float* crow = Cw + (size_t)m * H_DIM;
    float4 c0 = *(const float4*)(crow + 2 * jb);
    float4 c1 = *(const float4*)(crow + 2 * jb + 4);
    float4 pv = *(const float4*)(g_p + jb);
    float4 qv = *(const float4*)(g_q + jb);
    float4 r0 = *(const float4*)(g_rec + 2 * jb);
    float4 r1 = *(const float4*)(g_rec + 2 * jb + 4);
    float y0acc = c0.x * r0.x + c0.y * r0.y + c0.z * r0.z + c0.w * r0.w +
                  c1.x * r1.x + c1.y * r1.y + c1.z * r1.z + c1.w * r1.w;
    float o[8];
    o[0] =  c0.x * pv.x + c0.y * qv.x;  o[1] = -c0.x * qv.x + c0.y * pv.x;
    o[2] =  c0.z * pv.y + c0.w * qv.y;  o[3] = -c0.z * qv.y + c0.w * pv.y;
    o[4] =  c1.x * pv.z + c1.y * qv.z;  o[5] = -c1.x * qv.z + c1.y * pv.z;
    o[6] =  c1.z * pv.w + c1.w * qv.w;  o[7] = -c1.z * qv.w + c1.w * pv.w;
    unsigned short h[8], l[8];
#pragma unroll
    for (int i = 0; i < 8; i++) split1(o[i], h[i], l[i]);
    size_t vi = ((size_t)m * H_DIM + 2 * jb) / 8;
    g_Chi4[vi] = make_uint4(pkw(h[0], h[1]), pkw(h[2], h[3]), pkw(h[4], h[5]), pkw(h[6], h[7]));
    g_Clo4[vi] = make_uint4(pkw(l[0], l[1]), pkw(l[2], l[3]), pkw(l[4], l[5]), pkw(l[6], l[7]));
    __shared__ float red[256];
    red[threadIdx.x] = y0acc;
    __syncthreads();
    for (int off = 128; off > 0; off >>= 1) {
        if (threadIdx.x < off) red[threadIdx.x] += red[threadIdx.x + off];
        __syncthreads();
    }
    if (threadIdx.x == 0) g_y0p[m * 4 + blockIdx.x] = red[0];
}

// ---------------- kernel 2: Bw transpose + split -> BwT hi/lo [n][k] ----------------
__global__ __launch_bounds__(256) void bwsplit_kernel(const float* __restrict__ Bw) {
    __shared__ float tile[64][65];
    int k0 = blockIdx.x * 64, n0 = blockIdx.y * 64, t = threadIdx.x;
#pragma unroll
    for (int i = 0; i < 4; i++) {
        int idx = t + i * 256;
        int r = idx >> 4, c4 = idx & 15;
        float4 v = *(const float4*)&Bw[(size_t)(k0 + r) * KIN + n0 + c4 * 4];
        tile[r][c4 * 4 + 0] = v.x;
        tile[r][c4 * 4 + 1] = v.y;
        tile[r][c4 * 4 + 2] = v.z;
        tile[r][c4 * 4 + 3] = v.w;
    }
    __syncthreads();
#pragma unroll
    for (int i = 0; i < 2; i++) {
        int idx = t + i * 256;
        int nr = idx >> 3, q = idx & 7;
        unsigned short h[8], l[8];
#pragma unroll
        for (int e = 0; e < 8; e++) split1(tile[q * 8 + e][nr], h[e], l[e]);
        size_t vi = ((size_t)(n0 + nr) * H_DIM + k0 + q * 8) / 8;
        g_BwTh4[vi] = make_uint4(pkw(h[0], h[1]), pkw(h[2], h[3]), pkw(h[4], h[5]), pkw(h[6], h[7]));
        g_BwTl4[vi] = make_uint4(pkw(l[0], l[1]), pkw(l[2], l[3]), pkw(l[4], l[5]), pkw(l[6], l[7]));
    }
}

// ---------------- shared mma core: 3-term split with fragment sharing ----------------
// Per s-step: load the 8 (MT=2) / 6 (MT=1) unique fragments once, issue 12*MT mmas.
template <int MT>
__device__ __forceinline__ void mma3(int lane, int wm, int wn, float acc[][4][4],
                                     uint32_t ah, uint32_t al,
                                     uint32_t bh, uint32_t bl) {
#pragma unroll
    for (int s = 0; s < 4; s++) {
        uint32_t Ah[MT][4], Al[MT][4], Bh[2][4], Bl[2][4];
#pragma unroll
        for (int mt = 0; mt < MT; mt++) {
            int row = wm * (16 * MT) + mt * 16 + (lane & 15);
            int cb = s * 32 + ((lane >> 4) << 4);
            uint32_t o = SW128((uint32_t)(row * 128 + cb));
            ldsm_x4(Ah[mt], ah + o);
            ldsm_x4(Al[mt], al + o);
        }
#pragma unroll
        for (int nh = 0; nh < 2; nh++) {
            int row = wn * 32 + nh * 16 + (lane & 7) + ((lane & 16) ? 8 : 0);
            int cb = s * 32 + ((lane & 8) ? 16 : 0);
            uint32_t o = SW128((uint32_t)(row * 128 + cb));
            ldsm_x4(Bh[nh], bh + o);
            ldsm_x4(Bl[nh], bl + o);
        }
#pragma unroll
        for (int mt = 0; mt < MT; mt++)
#pragma unroll
            for (int nt = 0; nt < 4; nt++) {
                mma16816(acc[mt][nt], Ah[mt], &Bh[nt >> 1][(nt & 1) * 2]);
                mma16816(acc[mt][nt], Ah[mt], &Bl[nt >> 1][(nt & 1) * 2]);
                mma16816(acc[mt][nt], Al[mt], &Bh[nt >> 1][(nt & 1) * 2]);
            }
    }
}

// ---------------- gemmG tile prefetch (cp.async) ----------------
__device__ __forceinline__ void gemmG_load_stage(uint32_t sb, int t, int m0, int n0, int ktg) {
#pragma unroll
    for (int i = 0; i < 4; i++) {
        int idx = t + i * 256;
        int row = idx >> 3, q = idx & 7;
        uint32_t off = SW128((uint32_t)(row * 128 + q * 16));
        size_t src = (size_t)(m0 + row) * (H_DIM / 8) + ktg * 8 + q;
        cpa16(sb + off,         &g_Chi4[src]);
        cpa16(sb + 16384 + off, &g_Clo4[src]);
    }
#pragma unroll
    for (int i = 0; i < 2; i++) {
        int idx = t + i * 256;
        int row = idx >> 3, q = idx & 7;
        uint32_t off = SW128((uint32_t)(row * 128 + q * 16));
        size_t src = (size_t)(n0 + row) * (H_DIM / 8) + ktg * 8 + q;
        cpa16(sb + 32768 + off, &g_BwTh4[src]);
        cpa16(sb + 40960 + off, &g_BwTl4[src]);
    }
}

// ---------------- kernel 3: gemmG = C' @ BwT^T, 2-stage cp.async, 2 CTA/SM ----------------
// grid (5 n, 2 m, 32 splits) = 320 CTAs, 256 thr, CTA tile 128x64, 96KB dyn smem
__global__ __launch_bounds__(256, 2) void gemmG_kernel() {
    extern __shared__ __align__(128) char dsm[];
    uint32_t sb = smem_u32(dsm);
    int t = threadIdx.x;
    int lane = t & 31;
    int w = t >> 5;
    int wm = w >> 1, wn = w & 1;
    int n0 = blockIdx.x * 64, m0 = blockIdx.y * 128, sp = blockIdx.z;
    const int NT = KCHUNK / 64;
    int ktbase = sp * NT;
    float acc[2][4][4];
#pragma unroll
    for (int mt = 0; mt < 2; mt++)
#pragma unroll
        for (int nt = 0; nt < 4; nt++)
#pragma unroll
            for (int e = 0; e < 4; e++) acc[mt][nt][e] = 0.0f;

    gemmG_load_stage(sb, t, m0, n0, ktbase);
    CPA_COMMIT();
#pragma unroll 1
    for (int kt = 0; kt < NT; kt++) {
        __syncthreads();
        if (kt + 1 < NT) {
            gemmG_load_stage(sb + ((kt + 1) & 1) * STAGE_BYTES, t, m0, n0, ktbase + kt + 1);
            CPA_COMMIT();
            asm volatile("cp.async.wait_group 1;" ::: "memory");
        } else {
            asm volatile("cp.async.wait_group 0;" ::: "memory");
        }
        __syncthreads();
        uint32_t ss = sb + (kt & 1) * STAGE_BYTES;
        mma3<2>(lane, wm, wn, acc, ss, ss + 16384, ss + 32768, ss + 40960);
    }
    float* out = g_Gpart[sp];
    int gid = lane >> 2, tig = lane & 3;
#pragma unroll
    for (int mt = 0; mt < 2; mt++)
#pragma unroll
        for (int nt = 0; nt < 4; nt++) {
            int r0 = m0 + wm * 32 + mt * 16 + gid;
            int c = n0 + wn * 32 + nt * 8 + tig * 2;
            *(float2*)&out[(size_t)r0 * KIN + c] =
                make_float2(acc[mt][nt][0], acc[mt][nt][1]);
            *(float2*)&out[(size_t)(r0 + 8) * KIN + c] =
                make_float2(acc[mt][nt][2], acc[mt][nt][3]);
        }
}

// ---------------- kernel 4: split-K reduce -> G bf16 hi/lo + y0 ----------------
__global__ void reduceG_kernel() {
    int idx4 = blockIdx.x * blockDim.x + threadIdx.x;
    if (idx4 < Y_DIM * KIN / 4) {
        float4 s = make_float4(0.f, 0.f, 0.f, 0.f);
#pragma unroll
        for (int p = 0; p < GSPLITS; p++) {
            float4 v = *(const float4*)&g_Gpart[p][idx4 * 4];
            s.x += v.x; s.y += v.y; s.z += v.z; s.w += v.w;
        }
        unsigned short h[4], l[4];
        split1(s.x, h[0], l[0]); split1(s.y, h[1], l[1]);
        split1(s.z, h[2], l[2]); split1(s.w, h[3], l[3]);
        ((uint2*)g_Ghi4)[idx4] = make_uint2(pkw(h[0], h[1]), pkw(h[2], h[3]));
        ((uint2*)g_Glo4)[idx4] = make_uint2(pkw(l[0], l[1]), pkw(l[2], l[3]));
    }
    if (idx4 < Y_DIM) {
        g_y0[idx4] = (g_y0p[idx4 * 4 + 0] + g_y0p[idx4 * 4 + 1]) +
                     (g_y0p[idx4 * 4 + 2] + g_y0p[idx4 * 4 + 3]);
    }
}

// ---------------- kernel 5: finalY = y0 + udu @ G^T, A split on the fly ----------------
// grid (4 n, 128 m) = 512 CTAs, 128 thr, CTA tile 32x64, 24KB smem (~3.4 CTA/SM)
// smem: AH [0,4K) AL [4K,8K) BH [8K,16K) BL [16K,24K)
__global__ __launch_bounds__(128) void finalY_kernel(const float* __restrict__ u,
                                                     const float* __restrict__ du,
                                                     float* __restrict__ y) {
    __shared__ __align__(128) char sm[24576];
    uint32_t sb = smem_u32(sm);
    int t = threadIdx.x;
    int lane = t & 31;
    int w = t >> 5;
    int wm = w >> 1, wn = w & 1;
    int n0 = blockIdx.x * 64, m0 = blockIdx.y * 32;
    float acc[1][4][4];
#pragma unroll
    for (int nt = 0; nt < 4; nt++)
#pragma unroll
        for (int e = 0; e < 4; e++) acc[0][nt][e] = 0.0f;

#pragma unroll 1
    for (int kt = 0; kt < KIN / 64; kt++) {
        __syncthreads();
        // A: 32 rows x 64 k fp32, split in regs (du/u boundary tile-aligned)
#pragma unroll
        for (int i = 0; i < 4; i++) {
            int idx = t + i * 128;
            int row = idx >> 4, q4 = idx & 15;
            float4 v;
            if (kt == 0)
                v = *(const float4*)&du[(size_t)(m0 + row) * D_DIM + q4 * 4];
            else
                v = *(const float4*)&u[(size_t)(m0 + row) * U_DIM + (kt - 1) * 64 + q4 * 4];
            unsigned short h[4], l[4];
            split1(v.x, h[0], l[0]); split1(v.y, h[1], l[1]);
            split1(v.z, h[2], l[2]); split1(v.w, h[3], l[3]);
            uint32_t off = SW128((uint32_t)(row * 128 + (q4 >> 1) * 16)) + (q4 & 1) * 8;
            *(uint2*)(sm + off)        = make_uint2(pkw(h[0], h[1]), pkw(h[2], h[3]));
            *(uint2*)(sm + 4096 + off) = make_uint2(pkw(l[0], l[1]), pkw(l[2], l[3]));
        }
        // B: 64 rows(n) x 64 k bf16 hi/lo from G
#pragma unroll
        for (int i = 0; i < 4; i++) {
            int idx = t + i * 128;
            int row = idx >> 3, q = idx & 7;
            uint32_t off = SW128((uint32_t)(row * 128 + q * 16));
            size_t src = (size_t)(n0 + row) * (KIN / 8) + kt * 8 + q;
            *(uint4*)(sm + 8192 + off)  = g_Ghi4[src];
            *(uint4*)(sm + 16384 + off) = g_Glo4[src];
        }
        __syncthreads();
        mma3<1>(lane, wm, wn, acc, sb, sb + 4096, sb + 8192, sb + 16384);
    }
    int gid = lane >> 2, tig = lane & 3;
#pragma unroll
    for (int nt = 0; nt < 4; nt++) {
        int r0 = m0 + wm * 16 + gid;
        int c = n0 + wn * 32 + nt * 8 + tig * 2;
        float2 y0v = *(const float2*)&g_y0[c];
        *(float2*)&y[(size_t)r0 * Y_DIM + c] =
            make_float2(acc[0][nt][0] + y0v.x, acc[0][nt][1] + y0v.y);
        *(float2*)&y[(size_t)(r0 + 8) * Y_DIM + c] =
            make_float2(acc[0][nt][2] + y0v.x, acc[0][nt][3] + y0v.y);
    }
}

// ---------------- launch ----------------
extern "C" void kernel_launch(void* const* d_in, const int* in_sizes, int n_in,
                              void* d_out, int out_size) {
    const float *u = nullptr, *du = nullptr, *h = nullptr, *om = nullptr,
                *Bw = nullptr, *Cw = nullptr;
    for (int i = 0; i < n_in; i++) {
        switch (in_sizes[i]) {
            case B_N * U_DIM:   u  = (const float*)d_in[i]; break;
            case B_N * D_DIM:   du = (const float*)d_in[i]; break;
            case H_DIM:         h  = (const float*)d_in[i]; break;
            case ORD:           om = (const float*)d_in[i]; break;
            case H_DIM * KIN:   Bw = (const float*)d_in[i]; break;
            case Y_DIM * H_DIM: Cw = (const float*)d_in[i]; break;
            default: break;
        }
    }
    if (!u || !du || !h || !om || !Bw || !Cw) {
        u  = (const float*)d_in[0];
        du = (const float*)d_in[1];
        h  = (const float*)d_in[2];
        om = (const float*)d_in[3];
        Bw = (const float*)d_in[4];
        Cw = (const float*)d_in[5];
    }
    float* y = (float*)d_out;

    cudaFuncSetAttribute(gemmG_kernel,
                         cudaFuncAttributeMaxDynamicSharedMemorySize, 2 * STAGE_BYTES);

    coef_kernel<<<ORD / 256, 256>>>(om, h);
    prep_kernel<<<dim3(4, Y_DIM), 256>>>(Cw);
    bwsplit_kernel<<<dim3(H_DIM / 64, KIN / 64), 256>>>(Bw);
    gemmG_kernel<<<dim3(KIN / 64, Y_DIM / 128, GSPLITS), 256, 2 * STAGE_BYTES>>>();
    reduceG_kernel<<<(Y_DIM * KIN / 4 + 255) / 256, 256>>>();
    finalY_kernel<<<dim3(Y_DIM / 64, B_N / 32), 128>>>(u, du, y);
}